// round 1
// baseline (speedup 1.0000x reference)
#include <cuda_runtime.h>
#include <cstdint>

#define N_NODES 50000
#define E_EDGES 1600000
#define HDIM    256
#define CDIM    2

// ---------------------------------------------------------------------------
// Static device scratch (no runtime allocation allowed)
// ---------------------------------------------------------------------------
__device__ float g_deg[N_NODES];
__device__ float g_dis[N_NODES];
__device__ float g_norm[E_EDGES];
__device__ float g_buf0[(size_t)N_NODES * HDIM];
__device__ float g_buf1[(size_t)N_NODES * HDIM];
__device__ float g_buf2[(size_t)N_NODES * HDIM];
__device__ float g_buf3[(size_t)N_NODES * HDIM];

// ---------------------------------------------------------------------------
// Small helper kernels
// ---------------------------------------------------------------------------
__global__ void zero_deg_kernel() {
    int i = blockIdx.x * blockDim.x + threadIdx.x;
    if (i < N_NODES) g_deg[i] = 0.0f;
}

__global__ void count_deg_kernel(const int* __restrict__ src) {
    int e = blockIdx.x * blockDim.x + threadIdx.x;
    if (e < E_EDGES) atomicAdd(&g_deg[src[e]], 1.0f);
}

__global__ void dis_kernel() {
    int i = blockIdx.x * blockDim.x + threadIdx.x;
    if (i < N_NODES) {
        float d = g_deg[i];
        g_dis[i] = (d > 0.0f) ? rsqrtf(d) : 0.0f;
    }
}

__global__ void norm_kernel(const int* __restrict__ src, const int* __restrict__ dst) {
    int e = blockIdx.x * blockDim.x + threadIdx.x;
    if (e < E_EDGES) {
        g_norm[e] = -g_dis[src[e]] * g_dis[dst[e]];
    }
}

// ---------------------------------------------------------------------------
// SGEMM: C[M,256] = A[M,256] @ B[256,256]^T (+bias) (+relu)
// B is row-major [out, in] so both operands are K-contiguous.
// Tile: BM=128, BN=64, BK=16; 256 threads; 8x4 outputs per thread.
// ---------------------------------------------------------------------------
template <bool RELU, bool HAS_BIAS>
__global__ __launch_bounds__(256)
void gemm256_kernel(const float* __restrict__ A, const float* __restrict__ B,
                    const float* __restrict__ bias, float* __restrict__ C, int M)
{
    __shared__ float As[16][128];
    __shared__ float Bs[16][64];

    const int tid = threadIdx.x;
    const int rowBase = blockIdx.x * 128;
    const int colBase = blockIdx.y * 64;

    const int tm = tid >> 4;   // 0..15 -> rows tm*8 .. tm*8+7
    const int tn = tid & 15;   // 0..15 -> cols tn*4 .. tn*4+3

    float acc[8][4];
#pragma unroll
    for (int i = 0; i < 8; i++)
#pragma unroll
        for (int j = 0; j < 4; j++) acc[i][j] = 0.0f;

#pragma unroll 1
    for (int k0 = 0; k0 < 256; k0 += 16) {
        // Load A tile: 128x16 = 512 float4; 2 per thread.
#pragma unroll
        for (int i = 0; i < 2; i++) {
            int f   = tid + i * 256;
            int row = f >> 2;            // 0..127
            int kc  = (f & 3) * 4;       // 0,4,8,12
            int grow = rowBase + row;
            float4 v = make_float4(0.f, 0.f, 0.f, 0.f);
            if (grow < M)
                v = *(const float4*)(A + (size_t)grow * 256 + k0 + kc);
            As[kc + 0][row] = v.x;
            As[kc + 1][row] = v.y;
            As[kc + 2][row] = v.z;
            As[kc + 3][row] = v.w;
        }
        // Load B tile: 64x16 = 256 float4; 1 per thread.
        {
            int row = tid >> 2;          // 0..63
            int kc  = (tid & 3) * 4;
            float4 v = *(const float4*)(B + (size_t)(colBase + row) * 256 + k0 + kc);
            Bs[kc + 0][row] = v.x;
            Bs[kc + 1][row] = v.y;
            Bs[kc + 2][row] = v.z;
            Bs[kc + 3][row] = v.w;
        }
        __syncthreads();

#pragma unroll
        for (int kk = 0; kk < 16; kk++) {
            float a[8], b[4];
            *(float4*)(a)     = *(const float4*)&As[kk][tm * 8];
            *(float4*)(a + 4) = *(const float4*)&As[kk][tm * 8 + 4];
            *(float4*)(b)     = *(const float4*)&Bs[kk][tn * 4];
#pragma unroll
            for (int i = 0; i < 8; i++)
#pragma unroll
                for (int j = 0; j < 4; j++)
                    acc[i][j] = fmaf(a[i], b[j], acc[i][j]);
        }
        __syncthreads();
    }

    float4 bv = make_float4(0.f, 0.f, 0.f, 0.f);
    if (HAS_BIAS) bv = *(const float4*)(bias + colBase + tn * 4);

#pragma unroll
    for (int i = 0; i < 8; i++) {
        int grow = rowBase + tm * 8 + i;
        if (grow < M) {
            float4 o;
            o.x = acc[i][0] + bv.x;
            o.y = acc[i][1] + bv.y;
            o.z = acc[i][2] + bv.z;
            o.w = acc[i][3] + bv.w;
            if (RELU) {
                o.x = fmaxf(o.x, 0.f); o.y = fmaxf(o.y, 0.f);
                o.z = fmaxf(o.z, 0.f); o.w = fmaxf(o.w, 0.f);
            }
            *(float4*)(C + (size_t)grow * 256 + colBase + tn * 4) = o;
        }
    }
}

// ---------------------------------------------------------------------------
// Edge scatter: out[dst] += norm * g[src], 256 floats per edge.
// One warp per edge; vector f32 red atomics (sm_90+).
// ---------------------------------------------------------------------------
__device__ __forceinline__ void red_add_v4(float* addr, float4 v) {
    asm volatile("red.global.add.v4.f32 [%0], {%1, %2, %3, %4};"
                 :: "l"(addr), "f"(v.x), "f"(v.y), "f"(v.z), "f"(v.w)
                 : "memory");
}

__global__ __launch_bounds__(256)
void edge_scatter_kernel(const float* __restrict__ g, float* __restrict__ out,
                         const int* __restrict__ src, const int* __restrict__ dst)
{
    int warp = (blockIdx.x * blockDim.x + threadIdx.x) >> 5;
    int lane = threadIdx.x & 31;
    if (warp >= E_EDGES) return;

    int s = src[warp];
    int d = dst[warp];
    float w = g_norm[warp];

    const float4* gp = (const float4*)(g + (size_t)s * 256);
    float*        op = out + (size_t)d * 256;

    float4 v0 = gp[lane * 2];
    float4 v1 = gp[lane * 2 + 1];
    v0.x *= w; v0.y *= w; v0.z *= w; v0.w *= w;
    v1.x *= w; v1.y *= w; v1.z *= w; v1.w *= w;

    red_add_v4(op + lane * 8,     v0);
    red_add_v4(op + lane * 8 + 4, v1);
}

// ---------------------------------------------------------------------------
// Head: out[N,2] = h[N,256] @ W4[2,256]^T + b4. One warp per row.
// ---------------------------------------------------------------------------
__global__ __launch_bounds__(256)
void head_kernel(const float* __restrict__ h, const float* __restrict__ W4,
                 const float* __restrict__ b4, float* __restrict__ out)
{
    int warp = (blockIdx.x * blockDim.x + threadIdx.x) >> 5;
    int lane = threadIdx.x & 31;
    if (warp >= N_NODES) return;

    const float* hr = h + (size_t)warp * 256;
    float s0 = 0.f, s1 = 0.f;
#pragma unroll
    for (int i = 0; i < 8; i++) {
        int c = lane + i * 32;
        float v = hr[c];
        s0 = fmaf(v, W4[c],       s0);
        s1 = fmaf(v, W4[256 + c], s1);
    }
#pragma unroll
    for (int o = 16; o > 0; o >>= 1) {
        s0 += __shfl_down_sync(0xFFFFFFFFu, s0, o);
        s1 += __shfl_down_sync(0xFFFFFFFFu, s1, o);
    }
    if (lane == 0) {
        out[(size_t)warp * 2 + 0] = s0 + b4[0];
        out[(size_t)warp * 2 + 1] = s1 + b4[1];
    }
}

// ---------------------------------------------------------------------------
// Launch sequence
// ---------------------------------------------------------------------------
extern "C" void kernel_launch(void* const* d_in, const int* in_sizes, int n_in,
                              void* d_out, int out_size)
{
    const float* x    = (const float*)d_in[0];
    const int*   ei   = (const int*)  d_in[1];
    const float* W1   = (const float*)d_in[2];
    const float* b1   = (const float*)d_in[3];
    const float* W2   = (const float*)d_in[4];
    const float* b2   = (const float*)d_in[5];
    const float* W3   = (const float*)d_in[6];
    const float* b3   = (const float*)d_in[7];
    const float* W4   = (const float*)d_in[8];
    const float* b4   = (const float*)d_in[9];
    const float* T10  = (const float*)d_in[10];
    const float* T11  = (const float*)d_in[11];
    const float* cb1  = (const float*)d_in[12];
    const float* T20  = (const float*)d_in[13];
    const float* T21  = (const float*)d_in[14];
    const float* cb2  = (const float*)d_in[15];
    float* out = (float*)d_out;

    const int* src = ei;            // edge_index[0]
    const int* dst = ei + E_EDGES;  // edge_index[1]

    float *buf0, *buf1, *buf2, *buf3;
    cudaGetSymbolAddress((void**)&buf0, g_buf0);
    cudaGetSymbolAddress((void**)&buf1, g_buf1);
    cudaGetSymbolAddress((void**)&buf2, g_buf2);
    cudaGetSymbolAddress((void**)&buf3, g_buf3);

    // --- Normalization coefficients ---
    zero_deg_kernel<<<(N_NODES + 255) / 256, 256>>>();
    count_deg_kernel<<<(E_EDGES + 255) / 256, 256>>>(src);
    dis_kernel<<<(N_NODES + 255) / 256, 256>>>();
    norm_kernel<<<(E_EDGES + 255) / 256, 256>>>(src, dst);

    dim3 ggrid((N_NODES + 127) / 128, HDIM / 64);
    dim3 gblk(256);

    // h = relu(x@W1^T + b1) ; h = relu(h@W2^T + b2)
    gemm256_kernel<true, true><<<ggrid, gblk>>>(x,    W1, b1, buf0, N_NODES);
    gemm256_kernel<true, true><<<ggrid, gblk>>>(buf0, W2, b2, buf1, N_NODES);

    // Cheb conv 1: out1 = h@T10^T + S(h@T11^T) + cb1
    gemm256_kernel<false, false><<<ggrid, gblk>>>(buf1, T11, nullptr, buf2, N_NODES);
    gemm256_kernel<false, true ><<<ggrid, gblk>>>(buf1, T10, cb1,     buf3, N_NODES);
    edge_scatter_kernel<<<(E_EDGES * 32) / 256, 256>>>(buf2, buf3, src, dst);

    // Cheb conv 2: out2 = out1@T20^T + S(out1@T21^T) + cb2
    gemm256_kernel<false, false><<<ggrid, gblk>>>(buf3, T21, nullptr, buf2, N_NODES);
    gemm256_kernel<false, true ><<<ggrid, gblk>>>(buf3, T20, cb2,     buf0, N_NODES);
    edge_scatter_kernel<<<(E_EDGES * 32) / 256, 256>>>(buf2, buf0, src, dst);

    // h = relu(out2@W3^T + b3) ; out = h@W4^T + b4
    gemm256_kernel<true, true><<<ggrid, gblk>>>(buf0, W3, b3, buf1, N_NODES);
    head_kernel<<<(N_NODES * 32 + 255) / 256, 256>>>(buf1, W4, b4, out);
}

// round 3
// speedup vs baseline: 1.4062x; 1.4062x over previous
#include <cuda_runtime.h>
#include <cuda_bf16.h>
#include <cstdint>

#define N_NODES 50000
#define E_EDGES 1600000
#define HDIM    256

// ---------------------------------------------------------------------------
// Static device scratch (no runtime allocation allowed)
// ---------------------------------------------------------------------------
__device__ float g_deg[N_NODES];
__device__ float g_dis[N_NODES];
__device__ float g_norm[E_EDGES];
__device__ float g_buf0[(size_t)N_NODES * HDIM];
__device__ float g_buf1[(size_t)N_NODES * HDIM];
__device__ float g_buf2[(size_t)N_NODES * HDIM];
__device__ float g_buf3[(size_t)N_NODES * HDIM];

// ---------------------------------------------------------------------------
// mma.sync helpers (sm_80-era PTX; runs as HMMA fallback on sm_100)
// ---------------------------------------------------------------------------
__device__ __forceinline__ uint32_t pack_bf16x2(float lo, float hi) {
    // d[31:16] = cvt(first src), d[15:0] = cvt(second src)
    uint32_t u;
    asm("cvt.rn.bf16x2.f32 %0, %1, %2;" : "=r"(u) : "f"(hi), "f"(lo));
    return u;
}

__device__ __forceinline__ void ldsm_x4(uint32_t& r0, uint32_t& r1,
                                        uint32_t& r2, uint32_t& r3, uint32_t addr) {
    asm volatile("ldmatrix.sync.aligned.m8n8.x4.shared.b16 {%0,%1,%2,%3}, [%4];"
                 : "=r"(r0), "=r"(r1), "=r"(r2), "=r"(r3) : "r"(addr));
}

__device__ __forceinline__ void mma_bf16(float c[4], const uint32_t a[4],
                                         const uint32_t b[2]) {
    asm volatile(
        "mma.sync.aligned.m16n8k16.row.col.f32.bf16.bf16.f32 "
        "{%0,%1,%2,%3}, {%4,%5,%6,%7}, {%8,%9}, {%0,%1,%2,%3};"
        : "+f"(c[0]), "+f"(c[1]), "+f"(c[2]), "+f"(c[3])
        : "r"(a[0]), "r"(a[1]), "r"(a[2]), "r"(a[3]), "r"(b[0]), "r"(b[1]));
}

// ---------------------------------------------------------------------------
// bf16 3-pass split GEMM: C[M,256] = A[M,256] @ B[256,256]^T (+bias)(+relu)
// CTA tile 128x128x32. 8 warps, warp tile 32(M) x 64(N).
// K-stride padded to 40 bf16 (80B): ldmatrix rows land on distinct bank groups.
// ---------------------------------------------------------------------------
#define BM 128
#define BN 128
#define KS 40   // padded bf16 elements per SMEM row

template <bool RELU, bool HAS_BIAS>
__global__ __launch_bounds__(256, 2)
void gemm_mma_kernel(const float* __restrict__ A, const float* __restrict__ B,
                     const float* __restrict__ bias, float* __restrict__ C, int M)
{
    __shared__ __align__(16) unsigned short sA[2][BM][KS];  // [hi/lo][row][k]
    __shared__ __align__(16) unsigned short sB[2][BN][KS];

    const int tid  = threadIdx.x;
    const int lane = tid & 31;
    const int wid  = tid >> 5;
    const int wm   = (wid & 3) * 32;    // warp M offset 0..96
    const int wn   = (wid >> 2) * 64;   // warp N offset 0/64
    const int rowBase = blockIdx.x * BM;
    const int colBase = blockIdx.y * BN;

    const uint32_t aB0 = (uint32_t)__cvta_generic_to_shared(&sA[0][0][0]);
    const uint32_t aB1 = (uint32_t)__cvta_generic_to_shared(&sA[1][0][0]);
    const uint32_t bB0 = (uint32_t)__cvta_generic_to_shared(&sB[0][0][0]);
    const uint32_t bB1 = (uint32_t)__cvta_generic_to_shared(&sB[1][0][0]);

    float acc[2][8][4];
#pragma unroll
    for (int mi = 0; mi < 2; mi++)
#pragma unroll
        for (int ni = 0; ni < 8; ni++)
#pragma unroll
            for (int j = 0; j < 4; j++) acc[mi][ni][j] = 0.0f;

    // per-thread ldmatrix address offsets (in elements)
    const int aRow = wm + (lane & 15);
    const int aColSel = (lane >> 4) * 8;
    const int bRowA = wn + lane;          // group 0 (n-tiles 0..3)
    const int bRowB = wn + 32 + lane;     // group 1 (n-tiles 4..7)

#pragma unroll 1
    for (int chunk = 0; chunk < 8; ++chunk) {
        const int k0 = chunk * 32;

        // ---- load & split A tile: 128 x 32 floats ----
#pragma unroll
        for (int i = 0; i < 4; i++) {
            int f   = tid + i * 256;
            int row = f >> 3;
            int c4  = f & 7;
            int grow = rowBase + row;
            float4 v = make_float4(0.f, 0.f, 0.f, 0.f);
            if (grow < M) v = *(const float4*)(A + (size_t)grow * 256 + k0 + c4 * 4);
            float hx = __bfloat162float(__float2bfloat16_rn(v.x));
            float hy = __bfloat162float(__float2bfloat16_rn(v.y));
            float hz = __bfloat162float(__float2bfloat16_rn(v.z));
            float hw = __bfloat162float(__float2bfloat16_rn(v.w));
            uint2 hi = make_uint2(pack_bf16x2(v.x, v.y), pack_bf16x2(v.z, v.w));
            uint2 lo = make_uint2(pack_bf16x2(v.x - hx, v.y - hy),
                                  pack_bf16x2(v.z - hz, v.w - hw));
            *(uint2*)&sA[0][row][c4 * 4] = hi;
            *(uint2*)&sA[1][row][c4 * 4] = lo;
        }
        // ---- load & split B tile: 128 x 32 floats (colBase rows) ----
#pragma unroll
        for (int i = 0; i < 4; i++) {
            int f   = tid + i * 256;
            int row = f >> 3;
            int c4  = f & 7;
            float4 v = *(const float4*)(B + (size_t)(colBase + row) * 256 + k0 + c4 * 4);
            float hx = __bfloat162float(__float2bfloat16_rn(v.x));
            float hy = __bfloat162float(__float2bfloat16_rn(v.y));
            float hz = __bfloat162float(__float2bfloat16_rn(v.z));
            float hw = __bfloat162float(__float2bfloat16_rn(v.w));
            uint2 hi = make_uint2(pack_bf16x2(v.x, v.y), pack_bf16x2(v.z, v.w));
            uint2 lo = make_uint2(pack_bf16x2(v.x - hx, v.y - hy),
                                  pack_bf16x2(v.z - hz, v.w - hw));
            *(uint2*)&sB[0][row][c4 * 4] = hi;
            *(uint2*)&sB[1][row][c4 * 4] = lo;
        }
        __syncthreads();

        // ---- 3 split passes: hi*hi, hi*lo, lo*hi ----
#pragma unroll
        for (int pass = 0; pass < 3; ++pass) {
            const uint32_t aBase = (pass == 2) ? aB1 : aB0;
            const uint32_t bBase = (pass == 1) ? bB1 : bB0;
#pragma unroll
            for (int kk = 0; kk < 32; kk += 16) {
                uint32_t a[2][4];
#pragma unroll
                for (int mi = 0; mi < 2; mi++) {
                    uint32_t addr = aBase +
                        (uint32_t)(((aRow + mi * 16) * KS + kk + aColSel) * 2);
                    ldsm_x4(a[mi][0], a[mi][1], a[mi][2], a[mi][3], addr);
                }
                uint32_t b[8][2];
#pragma unroll
                for (int kh = 0; kh < 2; kh++) {
                    uint32_t r0, r1, r2, r3;
                    uint32_t addr = bBase + (uint32_t)((bRowA * KS + kk + kh * 8) * 2);
                    ldsm_x4(r0, r1, r2, r3, addr);
                    b[0][kh] = r0; b[1][kh] = r1; b[2][kh] = r2; b[3][kh] = r3;
                    addr = bBase + (uint32_t)((bRowB * KS + kk + kh * 8) * 2);
                    ldsm_x4(r0, r1, r2, r3, addr);
                    b[4][kh] = r0; b[5][kh] = r1; b[6][kh] = r2; b[7][kh] = r3;
                }
#pragma unroll
                for (int mi = 0; mi < 2; mi++)
#pragma unroll
                    for (int ni = 0; ni < 8; ni++)
                        mma_bf16(acc[mi][ni], a[mi], b[ni]);
            }
        }
        __syncthreads();
    }

    // ---- epilogue ----
#pragma unroll
    for (int mi = 0; mi < 2; mi++) {
        int row0 = rowBase + wm + mi * 16 + (lane >> 2);
        int row1 = row0 + 8;
#pragma unroll
        for (int ni = 0; ni < 8; ni++) {
            int col = colBase + wn + ni * 8 + (lane & 3) * 2;
            float bx = 0.f, by = 0.f;
            if (HAS_BIAS) { bx = __ldg(bias + col); by = __ldg(bias + col + 1); }
            float2 o0 = make_float2(acc[mi][ni][0] + bx, acc[mi][ni][1] + by);
            float2 o1 = make_float2(acc[mi][ni][2] + bx, acc[mi][ni][3] + by);
            if (RELU) {
                o0.x = fmaxf(o0.x, 0.f); o0.y = fmaxf(o0.y, 0.f);
                o1.x = fmaxf(o1.x, 0.f); o1.y = fmaxf(o1.y, 0.f);
            }
            if (row0 < M) *(float2*)(C + (size_t)row0 * 256 + col) = o0;
            if (row1 < M) *(float2*)(C + (size_t)row1 * 256 + col) = o1;
        }
    }
}

// ---------------------------------------------------------------------------
// Small helper kernels (norm precompute)
// ---------------------------------------------------------------------------
__global__ void zero_deg_kernel() {
    int i = blockIdx.x * blockDim.x + threadIdx.x;
    if (i < N_NODES) g_deg[i] = 0.0f;
}

__global__ void count_deg_kernel(const int* __restrict__ src) {
    int e = blockIdx.x * blockDim.x + threadIdx.x;
    if (e < E_EDGES) atomicAdd(&g_deg[src[e]], 1.0f);
}

__global__ void dis_kernel() {
    int i = blockIdx.x * blockDim.x + threadIdx.x;
    if (i < N_NODES) {
        float d = g_deg[i];
        g_dis[i] = (d > 0.0f) ? rsqrtf(d) : 0.0f;
    }
}

__global__ void norm_kernel(const int* __restrict__ src, const int* __restrict__ dst) {
    int e = blockIdx.x * blockDim.x + threadIdx.x;
    if (e < E_EDGES) {
        g_norm[e] = -g_dis[src[e]] * g_dis[dst[e]];
    }
}

// ---------------------------------------------------------------------------
// Edge scatter: out[dst] += norm * g[src], 256 floats/edge. One warp per edge.
// ---------------------------------------------------------------------------
__device__ __forceinline__ void red_add_v4(float* addr, float4 v) {
    asm volatile("red.global.add.v4.f32 [%0], {%1, %2, %3, %4};"
                 :: "l"(addr), "f"(v.x), "f"(v.y), "f"(v.z), "f"(v.w)
                 : "memory");
}

__global__ __launch_bounds__(256)
void edge_scatter_kernel(const float* __restrict__ g, float* __restrict__ out,
                         const int* __restrict__ src, const int* __restrict__ dst)
{
    int warp = (blockIdx.x * blockDim.x + threadIdx.x) >> 5;
    int lane = threadIdx.x & 31;
    if (warp >= E_EDGES) return;

    int s = src[warp];
    int d = dst[warp];
    float w = g_norm[warp];

    const float4* gp = (const float4*)(g + (size_t)s * 256);
    float*        op = out + (size_t)d * 256;

    float4 v0 = gp[lane * 2];
    float4 v1 = gp[lane * 2 + 1];
    v0.x *= w; v0.y *= w; v0.z *= w; v0.w *= w;
    v1.x *= w; v1.y *= w; v1.z *= w; v1.w *= w;

    red_add_v4(op + lane * 8,     v0);
    red_add_v4(op + lane * 8 + 4, v1);
}

// ---------------------------------------------------------------------------
// Head: out[N,2] = h[N,256] @ W4[2,256]^T + b4. One warp per row.
// ---------------------------------------------------------------------------
__global__ __launch_bounds__(256)
void head_kernel(const float* __restrict__ h, const float* __restrict__ W4,
                 const float* __restrict__ b4, float* __restrict__ out)
{
    int warp = (blockIdx.x * blockDim.x + threadIdx.x) >> 5;
    int lane = threadIdx.x & 31;
    if (warp >= N_NODES) return;

    const float* hr = h + (size_t)warp * 256;
    float s0 = 0.f, s1 = 0.f;
#pragma unroll
    for (int i = 0; i < 8; i++) {
        int c = lane + i * 32;
        float v = hr[c];
        s0 = fmaf(v, W4[c],       s0);
        s1 = fmaf(v, W4[256 + c], s1);
    }
#pragma unroll
    for (int o = 16; o > 0; o >>= 1) {
        s0 += __shfl_down_sync(0xFFFFFFFFu, s0, o);
        s1 += __shfl_down_sync(0xFFFFFFFFu, s1, o);
    }
    if (lane == 0) {
        out[(size_t)warp * 2 + 0] = s0 + b4[0];
        out[(size_t)warp * 2 + 1] = s1 + b4[1];
    }
}

// ---------------------------------------------------------------------------
// Launch sequence
// ---------------------------------------------------------------------------
extern "C" void kernel_launch(void* const* d_in, const int* in_sizes, int n_in,
                              void* d_out, int out_size)
{
    const float* x    = (const float*)d_in[0];
    const int*   ei   = (const int*)  d_in[1];
    const float* W1   = (const float*)d_in[2];
    const float* b1   = (const float*)d_in[3];
    const float* W2   = (const float*)d_in[4];
    const float* b2   = (const float*)d_in[5];
    const float* W3   = (const float*)d_in[6];
    const float* b3   = (const float*)d_in[7];
    const float* W4   = (const float*)d_in[8];
    const float* b4   = (const float*)d_in[9];
    const float* T10  = (const float*)d_in[10];
    const float* T11  = (const float*)d_in[11];
    const float* cb1  = (const float*)d_in[12];
    const float* T20  = (const float*)d_in[13];
    const float* T21  = (const float*)d_in[14];
    const float* cb2  = (const float*)d_in[15];
    float* out = (float*)d_out;

    const int* src = ei;            // edge_index[0]
    const int* dst = ei + E_EDGES;  // edge_index[1]

    float *buf0, *buf1, *buf2, *buf3;
    cudaGetSymbolAddress((void**)&buf0, g_buf0);
    cudaGetSymbolAddress((void**)&buf1, g_buf1);
    cudaGetSymbolAddress((void**)&buf2, g_buf2);
    cudaGetSymbolAddress((void**)&buf3, g_buf3);

    // --- Normalization coefficients ---
    zero_deg_kernel<<<(N_NODES + 255) / 256, 256>>>();
    count_deg_kernel<<<(E_EDGES + 255) / 256, 256>>>(src);
    dis_kernel<<<(N_NODES + 255) / 256, 256>>>();
    norm_kernel<<<(E_EDGES + 255) / 256, 256>>>(src, dst);

    dim3 ggrid((N_NODES + BM - 1) / BM, HDIM / BN);  // (391, 2)
    dim3 gblk(256);

    // h = relu(x@W1^T + b1) ; h = relu(h@W2^T + b2)
    gemm_mma_kernel<true, true><<<ggrid, gblk>>>(x,    W1, b1, buf0, N_NODES);
    gemm_mma_kernel<true, true><<<ggrid, gblk>>>(buf0, W2, b2, buf1, N_NODES);

    // Cheb conv 1: out1 = h@T10^T + S(h@T11^T) + cb1
    gemm_mma_kernel<false, false><<<ggrid, gblk>>>(buf1, T11, nullptr, buf2, N_NODES);
    gemm_mma_kernel<false, true ><<<ggrid, gblk>>>(buf1, T10, cb1,     buf3, N_NODES);
    edge_scatter_kernel<<<(E_EDGES * 32) / 256, 256>>>(buf2, buf3, src, dst);

    // Cheb conv 2: out2 = out1@T20^T + S(out1@T21^T) + cb2
    gemm_mma_kernel<false, false><<<ggrid, gblk>>>(buf3, T21, nullptr, buf2, N_NODES);
    gemm_mma_kernel<false, true ><<<ggrid, gblk>>>(buf3, T20, cb2,     buf0, N_NODES);
    edge_scatter_kernel<<<(E_EDGES * 32) / 256, 256>>>(buf2, buf0, src, dst);

    // h = relu(out2@W3^T + b3) ; out = h@W4^T + b4
    gemm_mma_kernel<true, true><<<ggrid, gblk>>>(buf0, W3, b3, buf1, N_NODES);
    head_kernel<<<(N_NODES * 32 + 255) / 256, 256>>>(buf1, W4, b4, out);
}

// round 4
// speedup vs baseline: 2.1489x; 1.5281x over previous
#include <cuda_runtime.h>
#include <cuda_bf16.h>
#include <cstdint>

#define N_NODES 50000
#define E_EDGES 1600000
#define HDIM    256

typedef unsigned short u16;

// ---------------------------------------------------------------------------
// Static device scratch (no runtime allocation allowed)
// ---------------------------------------------------------------------------
__device__ int   g_degi[N_NODES];      // out-degree of src (for dis)
__device__ int   g_cnt[N_NODES];       // in-degree at dst (CSR row counts)
__device__ int   g_rowstart[N_NODES];
__device__ int   g_cursor[N_NODES];
__device__ float g_dis[N_NODES];
__device__ int   g_csr_src[E_EDGES];
__device__ float g_csr_w[E_EDGES];

__device__ float g_buf0[(size_t)N_NODES * HDIM];   // fp32 scratch (g term)
__device__ float g_buf1[(size_t)N_NODES * HDIM];   // fp32 scratch (base term)
__device__ float g_buf2[(size_t)N_NODES * HDIM];   // fp32 h3

__device__ u16 g_ahi0[(size_t)N_NODES * HDIM];     // bf16 activation pair A
__device__ u16 g_alo0[(size_t)N_NODES * HDIM];
__device__ u16 g_ahi1[(size_t)N_NODES * HDIM];     // bf16 activation pair B
__device__ u16 g_alo1[(size_t)N_NODES * HDIM];

#define NW 7   // W1, W2, T11, T10, T21, T20, W3
__device__ u16 g_whi[NW * HDIM * HDIM];
__device__ u16 g_wlo[NW * HDIM * HDIM];

// ---------------------------------------------------------------------------
// helpers
// ---------------------------------------------------------------------------
__device__ __forceinline__ uint32_t pack_bf16x2(float lo, float hi) {
    uint32_t u;
    asm("cvt.rn.bf16x2.f32 %0, %1, %2;" : "=r"(u) : "f"(hi), "f"(lo));
    return u;
}

__device__ __forceinline__ void ldsm_x4(uint32_t& r0, uint32_t& r1,
                                        uint32_t& r2, uint32_t& r3, uint32_t addr) {
    asm volatile("ldmatrix.sync.aligned.m8n8.x4.shared.b16 {%0,%1,%2,%3}, [%4];"
                 : "=r"(r0), "=r"(r1), "=r"(r2), "=r"(r3) : "r"(addr));
}

__device__ __forceinline__ void mma_bf16(float c[4], const uint32_t a[4],
                                         const uint32_t b[2]) {
    asm volatile(
        "mma.sync.aligned.m16n8k16.row.col.f32.bf16.bf16.f32 "
        "{%0,%1,%2,%3}, {%4,%5,%6,%7}, {%8,%9}, {%0,%1,%2,%3};"
        : "+f"(c[0]), "+f"(c[1]), "+f"(c[2]), "+f"(c[3])
        : "r"(a[0]), "r"(a[1]), "r"(a[2]), "r"(a[3]), "r"(b[0]), "r"(b[1]));
}

// ---------------------------------------------------------------------------
// fp32 -> bf16 hi/lo split (vectorized x4)
// ---------------------------------------------------------------------------
__global__ void split_kernel(const float* __restrict__ in, u16* __restrict__ hi,
                             u16* __restrict__ lo, int n4)
{
    int i = blockIdx.x * blockDim.x + threadIdx.x;
    if (i >= n4) return;
    float4 v = ((const float4*)in)[i];
    float hx = __bfloat162float(__float2bfloat16_rn(v.x));
    float hy = __bfloat162float(__float2bfloat16_rn(v.y));
    float hz = __bfloat162float(__float2bfloat16_rn(v.z));
    float hw = __bfloat162float(__float2bfloat16_rn(v.w));
    uint2 h = make_uint2(pack_bf16x2(v.x, v.y), pack_bf16x2(v.z, v.w));
    uint2 l = make_uint2(pack_bf16x2(v.x - hx, v.y - hy),
                         pack_bf16x2(v.z - hz, v.w - hw));
    ((uint2*)hi)[i] = h;
    ((uint2*)lo)[i] = l;
}

// ---------------------------------------------------------------------------
// bf16 3-pass split GEMM, pre-split inputs.
// C[M,256] = A[M,256] @ W[256,256]^T (+bias)(+relu)
// CTA tile 128x128x32, 8 warps, warp tile 32x64, KS=40 padding.
// ---------------------------------------------------------------------------
#define BM 128
#define BN 128
#define KS 40

template <bool RELU, bool HAS_BIAS, bool OUTF32, bool OUTBF16>
__global__ __launch_bounds__(256, 2)
void gemm_mma_kernel(const u16* __restrict__ Ahi, const u16* __restrict__ Alo,
                     const u16* __restrict__ Whi, const u16* __restrict__ Wlo,
                     const float* __restrict__ bias,
                     float* __restrict__ C, u16* __restrict__ Chi,
                     u16* __restrict__ Clo, int M)
{
    __shared__ __align__(16) u16 sA[2][BM][KS];
    __shared__ __align__(16) u16 sB[2][BN][KS];

    const int tid  = threadIdx.x;
    const int lane = tid & 31;
    const int wid  = tid >> 5;
    const int wm   = (wid & 3) * 32;
    const int wn   = (wid >> 2) * 64;
    const int rowBase = blockIdx.x * BM;
    const int colBase = blockIdx.y * BN;

    const uint32_t aB0 = (uint32_t)__cvta_generic_to_shared(&sA[0][0][0]);
    const uint32_t aB1 = (uint32_t)__cvta_generic_to_shared(&sA[1][0][0]);
    const uint32_t bB0 = (uint32_t)__cvta_generic_to_shared(&sB[0][0][0]);
    const uint32_t bB1 = (uint32_t)__cvta_generic_to_shared(&sB[1][0][0]);

    float acc[2][8][4];
#pragma unroll
    for (int mi = 0; mi < 2; mi++)
#pragma unroll
        for (int ni = 0; ni < 8; ni++)
#pragma unroll
            for (int j = 0; j < 4; j++) acc[mi][ni][j] = 0.0f;

    const int aRow = wm + (lane & 15);
    const int aColSel = (lane >> 4) * 8;
    const int bRowA = wn + lane;
    const int bRowB = wn + 32 + lane;

#pragma unroll 1
    for (int chunk = 0; chunk < 8; ++chunk) {
        const int k0 = chunk * 32;
        // each thread: 2 uint4 per matrix (A hi/lo, W hi/lo)
#pragma unroll
        for (int i = 0; i < 2; i++) {
            int f   = tid + i * 256;
            int row = f >> 2;          // 0..127
            int c8  = (f & 3) * 8;     // 0,8,16,24
            int grow = rowBase + row;
            uint4 vh = make_uint4(0u, 0u, 0u, 0u), vl = vh;
            if (grow < M) {
                vh = *(const uint4*)(Ahi + (size_t)grow * 256 + k0 + c8);
                vl = *(const uint4*)(Alo + (size_t)grow * 256 + k0 + c8);
            }
            *(uint4*)&sA[0][row][c8] = vh;
            *(uint4*)&sA[1][row][c8] = vl;
            uint4 wh = *(const uint4*)(Whi + (size_t)(colBase + row) * 256 + k0 + c8);
            uint4 wl = *(const uint4*)(Wlo + (size_t)(colBase + row) * 256 + k0 + c8);
            *(uint4*)&sB[0][row][c8] = wh;
            *(uint4*)&sB[1][row][c8] = wl;
        }
        __syncthreads();

#pragma unroll
        for (int pass = 0; pass < 3; ++pass) {
            const uint32_t aBase = (pass == 2) ? aB1 : aB0;
            const uint32_t bBase = (pass == 1) ? bB1 : bB0;
#pragma unroll
            for (int kk = 0; kk < 32; kk += 16) {
                uint32_t a[2][4];
#pragma unroll
                for (int mi = 0; mi < 2; mi++) {
                    uint32_t addr = aBase +
                        (uint32_t)(((aRow + mi * 16) * KS + kk + aColSel) * 2);
                    ldsm_x4(a[mi][0], a[mi][1], a[mi][2], a[mi][3], addr);
                }
                uint32_t b[8][2];
#pragma unroll
                for (int kh = 0; kh < 2; kh++) {
                    uint32_t r0, r1, r2, r3;
                    uint32_t addr = bBase + (uint32_t)((bRowA * KS + kk + kh * 8) * 2);
                    ldsm_x4(r0, r1, r2, r3, addr);
                    b[0][kh] = r0; b[1][kh] = r1; b[2][kh] = r2; b[3][kh] = r3;
                    addr = bBase + (uint32_t)((bRowB * KS + kk + kh * 8) * 2);
                    ldsm_x4(r0, r1, r2, r3, addr);
                    b[4][kh] = r0; b[5][kh] = r1; b[6][kh] = r2; b[7][kh] = r3;
                }
#pragma unroll
                for (int mi = 0; mi < 2; mi++)
#pragma unroll
                    for (int ni = 0; ni < 8; ni++)
                        mma_bf16(acc[mi][ni], a[mi], b[ni]);
            }
        }
        __syncthreads();
    }

    // ---- epilogue ----
#pragma unroll
    for (int mi = 0; mi < 2; mi++) {
        int row0 = rowBase + wm + mi * 16 + (lane >> 2);
        int row1 = row0 + 8;
#pragma unroll
        for (int ni = 0; ni < 8; ni++) {
            int col = colBase + wn + ni * 8 + (lane & 3) * 2;
            float bx = 0.f, by = 0.f;
            if (HAS_BIAS) { bx = __ldg(bias + col); by = __ldg(bias + col + 1); }
            float2 o0 = make_float2(acc[mi][ni][0] + bx, acc[mi][ni][1] + by);
            float2 o1 = make_float2(acc[mi][ni][2] + bx, acc[mi][ni][3] + by);
            if (RELU) {
                o0.x = fmaxf(o0.x, 0.f); o0.y = fmaxf(o0.y, 0.f);
                o1.x = fmaxf(o1.x, 0.f); o1.y = fmaxf(o1.y, 0.f);
            }
            if (OUTF32) {
                if (row0 < M) *(float2*)(C + (size_t)row0 * 256 + col) = o0;
                if (row1 < M) *(float2*)(C + (size_t)row1 * 256 + col) = o1;
            }
            if (OUTBF16) {
                if (row0 < M) {
                    float hx = __bfloat162float(__float2bfloat16_rn(o0.x));
                    float hy = __bfloat162float(__float2bfloat16_rn(o0.y));
                    *(uint32_t*)(Chi + (size_t)row0 * 256 + col) = pack_bf16x2(o0.x, o0.y);
                    *(uint32_t*)(Clo + (size_t)row0 * 256 + col) =
                        pack_bf16x2(o0.x - hx, o0.y - hy);
                }
                if (row1 < M) {
                    float hx = __bfloat162float(__float2bfloat16_rn(o1.x));
                    float hy = __bfloat162float(__float2bfloat16_rn(o1.y));
                    *(uint32_t*)(Chi + (size_t)row1 * 256 + col) = pack_bf16x2(o1.x, o1.y);
                    *(uint32_t*)(Clo + (size_t)row1 * 256 + col) =
                        pack_bf16x2(o1.x - hx, o1.y - hy);
                }
            }
        }
    }
}

// ---------------------------------------------------------------------------
// CSR build
// ---------------------------------------------------------------------------
__global__ void zero_cnt_kernel() {
    int i = blockIdx.x * blockDim.x + threadIdx.x;
    if (i < N_NODES) { g_degi[i] = 0; g_cnt[i] = 0; }
}

__global__ void hist_kernel(const int* __restrict__ src, const int* __restrict__ dst) {
    int e = blockIdx.x * blockDim.x + threadIdx.x;
    if (e < E_EDGES) {
        atomicAdd(&g_degi[src[e]], 1);
        atomicAdd(&g_cnt[dst[e]], 1);
    }
}

__global__ void dis_kernel() {
    int i = blockIdx.x * blockDim.x + threadIdx.x;
    if (i < N_NODES) {
        int d = g_degi[i];
        g_dis[i] = (d > 0) ? rsqrtf((float)d) : 0.0f;
    }
}

__global__ __launch_bounds__(1024)
void scan_kernel() {
    __shared__ int ssum[1024];
    const int tid = threadIdx.x;
    const int CH = (N_NODES + 1023) / 1024;  // 49
    int s = 0;
#pragma unroll 1
    for (int j = 0; j < CH; j++) {
        int i = tid * CH + j;
        if (i < N_NODES) s += g_cnt[i];
    }
    ssum[tid] = s;
    __syncthreads();
#pragma unroll 1
    for (int off = 1; off < 1024; off <<= 1) {
        int v = (tid >= off) ? ssum[tid - off] : 0;
        __syncthreads();
        ssum[tid] += v;
        __syncthreads();
    }
    int run = ssum[tid] - s;   // exclusive prefix
#pragma unroll 1
    for (int j = 0; j < CH; j++) {
        int i = tid * CH + j;
        if (i < N_NODES) {
            g_rowstart[i] = run;
            g_cursor[i]   = run;
            run += g_cnt[i];
        }
    }
}

__global__ void fill_kernel(const int* __restrict__ src, const int* __restrict__ dst) {
    int e = blockIdx.x * blockDim.x + threadIdx.x;
    if (e < E_EDGES) {
        int s = src[e], d = dst[e];
        int pos = atomicAdd(&g_cursor[d], 1);
        g_csr_src[pos] = s;
        g_csr_w[pos]   = -g_dis[s] * g_dis[d];
    }
}

// ---------------------------------------------------------------------------
// Gather aggregation: out[n] = base[n] + sum_e w_e * g[src_e]; writes bf16 hi/lo.
// One warp per node; lane handles 8 consecutive columns.
// ---------------------------------------------------------------------------
__global__ __launch_bounds__(256)
void gather_kernel(const float* __restrict__ g, const float* __restrict__ base,
                   u16* __restrict__ outhi, u16* __restrict__ outlo)
{
    int node = (blockIdx.x * blockDim.x + threadIdx.x) >> 5;
    int lane = threadIdx.x & 31;
    if (node >= N_NODES) return;

    const float* bp = base + (size_t)node * 256 + lane * 8;
    float4 a0 = *(const float4*)(bp);
    float4 a1 = *(const float4*)(bp + 4);

    int p   = g_rowstart[node];
    int end = p + g_cnt[node];
#pragma unroll 1
    for (; p < end; ++p) {
        int   s = g_csr_src[p];
        float w = g_csr_w[p];
        const float4* gp = (const float4*)(g + (size_t)s * 256 + lane * 8);
        float4 v0 = gp[0];
        float4 v1 = gp[1];
        a0.x = fmaf(w, v0.x, a0.x); a0.y = fmaf(w, v0.y, a0.y);
        a0.z = fmaf(w, v0.z, a0.z); a0.w = fmaf(w, v0.w, a0.w);
        a1.x = fmaf(w, v1.x, a1.x); a1.y = fmaf(w, v1.y, a1.y);
        a1.z = fmaf(w, v1.z, a1.z); a1.w = fmaf(w, v1.w, a1.w);
    }

    float h0 = __bfloat162float(__float2bfloat16_rn(a0.x));
    float h1 = __bfloat162float(__float2bfloat16_rn(a0.y));
    float h2 = __bfloat162float(__float2bfloat16_rn(a0.z));
    float h3 = __bfloat162float(__float2bfloat16_rn(a0.w));
    float h4 = __bfloat162float(__float2bfloat16_rn(a1.x));
    float h5 = __bfloat162float(__float2bfloat16_rn(a1.y));
    float h6 = __bfloat162float(__float2bfloat16_rn(a1.z));
    float h7 = __bfloat162float(__float2bfloat16_rn(a1.w));

    uint4 hh, ll;
    hh.x = pack_bf16x2(a0.x, a0.y); hh.y = pack_bf16x2(a0.z, a0.w);
    hh.z = pack_bf16x2(a1.x, a1.y); hh.w = pack_bf16x2(a1.z, a1.w);
    ll.x = pack_bf16x2(a0.x - h0, a0.y - h1);
    ll.y = pack_bf16x2(a0.z - h2, a0.w - h3);
    ll.z = pack_bf16x2(a1.x - h4, a1.y - h5);
    ll.w = pack_bf16x2(a1.z - h6, a1.w - h7);

    *(uint4*)(outhi + (size_t)node * 256 + lane * 8) = hh;
    *(uint4*)(outlo + (size_t)node * 256 + lane * 8) = ll;
}

// ---------------------------------------------------------------------------
// Head: out[N,2] = h[N,256] @ W4[2,256]^T + b4. One warp per row.
// ---------------------------------------------------------------------------
__global__ __launch_bounds__(256)
void head_kernel(const float* __restrict__ h, const float* __restrict__ W4,
                 const float* __restrict__ b4, float* __restrict__ out)
{
    int warp = (blockIdx.x * blockDim.x + threadIdx.x) >> 5;
    int lane = threadIdx.x & 31;
    if (warp >= N_NODES) return;

    const float* hr = h + (size_t)warp * 256;
    float s0 = 0.f, s1 = 0.f;
#pragma unroll
    for (int i = 0; i < 8; i++) {
        int c = lane + i * 32;
        float v = hr[c];
        s0 = fmaf(v, W4[c],       s0);
        s1 = fmaf(v, W4[256 + c], s1);
    }
#pragma unroll
    for (int o = 16; o > 0; o >>= 1) {
        s0 += __shfl_down_sync(0xFFFFFFFFu, s0, o);
        s1 += __shfl_down_sync(0xFFFFFFFFu, s1, o);
    }
    if (lane == 0) {
        out[(size_t)warp * 2 + 0] = s0 + b4[0];
        out[(size_t)warp * 2 + 1] = s1 + b4[1];
    }
}

// ---------------------------------------------------------------------------
// Launch sequence
// ---------------------------------------------------------------------------
extern "C" void kernel_launch(void* const* d_in, const int* in_sizes, int n_in,
                              void* d_out, int out_size)
{
    const float* x    = (const float*)d_in[0];
    const int*   ei   = (const int*)  d_in[1];
    const float* W1   = (const float*)d_in[2];
    const float* b1   = (const float*)d_in[3];
    const float* W2   = (const float*)d_in[4];
    const float* b2   = (const float*)d_in[5];
    const float* W3   = (const float*)d_in[6];
    const float* b3   = (const float*)d_in[7];
    const float* W4   = (const float*)d_in[8];
    const float* b4   = (const float*)d_in[9];
    const float* T10  = (const float*)d_in[10];
    const float* T11  = (const float*)d_in[11];
    const float* cb1  = (const float*)d_in[12];
    const float* T20  = (const float*)d_in[13];
    const float* T21  = (const float*)d_in[14];
    const float* cb2  = (const float*)d_in[15];
    float* out = (float*)d_out;

    const int* src = ei;
    const int* dst = ei + E_EDGES;

    float *buf0, *buf1, *buf2;
    u16 *ahi0, *alo0, *ahi1, *alo1, *whi, *wlo;
    cudaGetSymbolAddress((void**)&buf0, g_buf0);
    cudaGetSymbolAddress((void**)&buf1, g_buf1);
    cudaGetSymbolAddress((void**)&buf2, g_buf2);
    cudaGetSymbolAddress((void**)&ahi0, g_ahi0);
    cudaGetSymbolAddress((void**)&alo0, g_alo0);
    cudaGetSymbolAddress((void**)&ahi1, g_ahi1);
    cudaGetSymbolAddress((void**)&alo1, g_alo1);
    cudaGetSymbolAddress((void**)&whi, g_whi);
    cudaGetSymbolAddress((void**)&wlo, g_wlo);

    const int WSZ = HDIM * HDIM;  // 65536

    // --- CSR + norm precompute ---
    zero_cnt_kernel<<<(N_NODES + 255) / 256, 256>>>();
    hist_kernel<<<(E_EDGES + 255) / 256, 256>>>(src, dst);
    dis_kernel<<<(N_NODES + 255) / 256, 256>>>();
    scan_kernel<<<1, 1024>>>();
    fill_kernel<<<(E_EDGES + 255) / 256, 256>>>(src, dst);

    // --- splits ---
    split_kernel<<<(N_NODES * HDIM / 4 + 255) / 256, 256>>>(x, ahi0, alo0,
                                                            N_NODES * HDIM / 4);
    const float* wsrc[NW] = {W1, W2, T11, T10, T21, T20, W3};
    for (int i = 0; i < NW; i++)
        split_kernel<<<(WSZ / 4 + 255) / 256, 256>>>(wsrc[i], whi + i * WSZ,
                                                     wlo + i * WSZ, WSZ / 4);

    dim3 ggrid((N_NODES + BM - 1) / BM, HDIM / BN);
    dim3 gblk(256);
    const int gthr = (N_NODES * 32 + 255) / 256;

    // h1 = relu(x@W1^T+b1) -> bf16 pair 1
    gemm_mma_kernel<true, true, false, true><<<ggrid, gblk>>>(
        ahi0, alo0, whi + 0 * WSZ, wlo + 0 * WSZ, b1, nullptr, ahi1, alo1, N_NODES);
    // h2 = relu(h1@W2^T+b2) -> bf16 pair 0
    gemm_mma_kernel<true, true, false, true><<<ggrid, gblk>>>(
        ahi1, alo1, whi + 1 * WSZ, wlo + 1 * WSZ, b2, nullptr, ahi0, alo0, N_NODES);
    // g = h2@T11^T -> f32 buf0 ; base = h2@T10^T+cb1 -> f32 buf1
    gemm_mma_kernel<false, false, true, false><<<ggrid, gblk>>>(
        ahi0, alo0, whi + 2 * WSZ, wlo + 2 * WSZ, nullptr, buf0, nullptr, nullptr, N_NODES);
    gemm_mma_kernel<false, true, true, false><<<ggrid, gblk>>>(
        ahi0, alo0, whi + 3 * WSZ, wlo + 3 * WSZ, cb1, buf1, nullptr, nullptr, N_NODES);
    // out1 = base + S g -> bf16 pair 1
    gather_kernel<<<gthr, 256>>>(buf0, buf1, ahi1, alo1);

    // g = out1@T21^T ; base = out1@T20^T+cb2
    gemm_mma_kernel<false, false, true, false><<<ggrid, gblk>>>(
        ahi1, alo1, whi + 4 * WSZ, wlo + 4 * WSZ, nullptr, buf0, nullptr, nullptr, N_NODES);
    gemm_mma_kernel<false, true, true, false><<<ggrid, gblk>>>(
        ahi1, alo1, whi + 5 * WSZ, wlo + 5 * WSZ, cb2, buf1, nullptr, nullptr, N_NODES);
    // out2 = base + S g -> bf16 pair 0
    gather_kernel<<<gthr, 256>>>(buf0, buf1, ahi0, alo0);

    // h3 = relu(out2@W3^T+b3) -> f32 buf2
    gemm_mma_kernel<true, true, true, false><<<ggrid, gblk>>>(
        ahi0, alo0, whi + 6 * WSZ, wlo + 6 * WSZ, b3, buf2, nullptr, nullptr, N_NODES);
    // out = h3@W4^T + b4
    head_kernel<<<gthr, 256>>>(buf2, W4, b4, out);
}

// round 5
// speedup vs baseline: 2.2840x; 1.0629x over previous
#include <cuda_runtime.h>
#include <cuda_bf16.h>
#include <cstdint>

#define N_NODES 50000
#define MPAD    50048
#define E_EDGES 1600000
#define HDIM    256
#define NBLK    196       // ceil(50000/256)

typedef unsigned short u16;

// ---------------------------------------------------------------------------
// Static device scratch
// ---------------------------------------------------------------------------
__device__ int   g_degi[N_NODES];
__device__ int   g_cnt[N_NODES];
__device__ int   g_rowstart[N_NODES];
__device__ int   g_cursor[N_NODES];
__device__ float g_dis[N_NODES];
__device__ int   g_csr_src[E_EDGES];
__device__ float g_csr_w[E_EDGES];
__device__ int   g_bsum[256];
__device__ int   g_boff[256];

__device__ float g_buf0[(size_t)MPAD * HDIM];
__device__ float g_buf1[(size_t)MPAD * HDIM];
__device__ float g_buf2[(size_t)MPAD * HDIM];

__device__ u16 g_ahi0[(size_t)MPAD * HDIM];
__device__ u16 g_alo0[(size_t)MPAD * HDIM];
__device__ u16 g_ahi1[(size_t)MPAD * HDIM];
__device__ u16 g_alo1[(size_t)MPAD * HDIM];

#define NW 7   // W1, W2, T11, T10, T21, T20, W3
__device__ u16 g_whi[NW * HDIM * HDIM];
__device__ u16 g_wlo[NW * HDIM * HDIM];

// ---------------------------------------------------------------------------
// helpers
// ---------------------------------------------------------------------------
__device__ __forceinline__ uint32_t pack_bf16x2(float lo, float hi) {
    uint32_t u;
    asm("cvt.rn.bf16x2.f32 %0, %1, %2;" : "=r"(u) : "f"(hi), "f"(lo));
    return u;
}

__device__ __forceinline__ void ldsm_x4(uint32_t& r0, uint32_t& r1,
                                        uint32_t& r2, uint32_t& r3, uint32_t addr) {
    asm volatile("ldmatrix.sync.aligned.m8n8.x4.shared.b16 {%0,%1,%2,%3}, [%4];"
                 : "=r"(r0), "=r"(r1), "=r"(r2), "=r"(r3) : "r"(addr));
}

__device__ __forceinline__ void mma_bf16(float c[4], const uint32_t a[4],
                                         const uint32_t b[2]) {
    asm volatile(
        "mma.sync.aligned.m16n8k16.row.col.f32.bf16.bf16.f32 "
        "{%0,%1,%2,%3}, {%4,%5,%6,%7}, {%8,%9}, {%0,%1,%2,%3};"
        : "+f"(c[0]), "+f"(c[1]), "+f"(c[2]), "+f"(c[3])
        : "r"(a[0]), "r"(a[1]), "r"(a[2]), "r"(a[3]), "r"(b[0]), "r"(b[1]));
}

#define CP16(sm, gp) \
    asm volatile("cp.async.cg.shared.global [%0], [%1], 16;" :: "r"(sm), "l"(gp))
#define CPCOMMIT() asm volatile("cp.async.commit_group;")
#define CPWAIT0()  asm volatile("cp.async.wait_group 0;")

// ---------------------------------------------------------------------------
// fp32 -> bf16 hi/lo split
// ---------------------------------------------------------------------------
__global__ void split_kernel(const float* __restrict__ in, u16* __restrict__ hi,
                             u16* __restrict__ lo, int n4)
{
    int i = blockIdx.x * blockDim.x + threadIdx.x;
    if (i >= n4) return;
    float4 v = ((const float4*)in)[i];
    float hx = __bfloat162float(__float2bfloat16_rn(v.x));
    float hy = __bfloat162float(__float2bfloat16_rn(v.y));
    float hz = __bfloat162float(__float2bfloat16_rn(v.z));
    float hw = __bfloat162float(__float2bfloat16_rn(v.w));
    uint2 h = make_uint2(pack_bf16x2(v.x, v.y), pack_bf16x2(v.z, v.w));
    uint2 l = make_uint2(pack_bf16x2(v.x - hx, v.y - hy),
                         pack_bf16x2(v.z - hz, v.w - hw));
    ((uint2*)hi)[i] = h;
    ((uint2*)lo)[i] = l;
}

// ---------------------------------------------------------------------------
// GEMM: C[MPAD,256] = A @ W^T (+bias)(+relu). Tile 128x256x32, 512 thr,
// 2-stage cp.async double buffer, bf16 3-pass split, KS=40 padding.
// ---------------------------------------------------------------------------
#define BM   128
#define KS   40
#define STG  61440
#define OA_HI 0
#define OA_LO 10240
#define OB_HI 20480
#define OB_LO 40960

template <bool RELU, bool HAS_BIAS, bool OUTF32, bool OUTBF16>
__global__ __launch_bounds__(512, 1)
void gemm_mma_kernel(const u16* __restrict__ Ahi, const u16* __restrict__ Alo,
                     const u16* __restrict__ Whi, const u16* __restrict__ Wlo,
                     const float* __restrict__ bias,
                     float* __restrict__ C, u16* __restrict__ Chi,
                     u16* __restrict__ Clo)
{
    extern __shared__ char smem[];
    const uint32_t sb = (uint32_t)__cvta_generic_to_shared(smem);
    const int tid  = threadIdx.x;
    const int lane = tid & 31;
    const int wid  = tid >> 5;
    const int wm   = (wid & 3) * 32;
    const int wn   = (wid >> 2) * 64;
    const int rowBase = blockIdx.x * BM;

    const int lrow = tid >> 2;          // 0..127
    const int lc8  = (tid & 3) * 8;     // 0,8,16,24

    float acc[2][8][4];
#pragma unroll
    for (int mi = 0; mi < 2; mi++)
#pragma unroll
        for (int ni = 0; ni < 8; ni++)
#pragma unroll
            for (int j = 0; j < 4; j++) acc[mi][ni][j] = 0.0f;

    const int aRow = wm + (lane & 15);
    const int aColSel = (lane >> 4) * 8;
    const int bRowA = wn + lane;
    const int bRowB = wn + 32 + lane;

    // ---- stage loader ----
    auto load_chunk = [&](int k0, int s) {
        uint32_t base = sb + (uint32_t)s * STG;
        uint32_t so = (uint32_t)(lrow * 80 + lc8 * 2);
        CP16(base + OA_HI + so, Ahi + (size_t)(rowBase + lrow) * 256 + k0 + lc8);
        CP16(base + OA_LO + so, Alo + (size_t)(rowBase + lrow) * 256 + k0 + lc8);
        CP16(base + OB_HI + so, Whi + (size_t)lrow * 256 + k0 + lc8);
        CP16(base + OB_LO + so, Wlo + (size_t)lrow * 256 + k0 + lc8);
        uint32_t so2 = so + 128 * 80;
        CP16(base + OB_HI + so2, Whi + (size_t)(lrow + 128) * 256 + k0 + lc8);
        CP16(base + OB_LO + so2, Wlo + (size_t)(lrow + 128) * 256 + k0 + lc8);
    };

    load_chunk(0, 0);
    CPCOMMIT();

#pragma unroll 1
    for (int c = 0; c < 8; ++c) {
        const int s = c & 1;
        CPWAIT0();
        __syncthreads();
        if (c < 7) { load_chunk((c + 1) * 32, s ^ 1); CPCOMMIT(); }

        const uint32_t stgBase = sb + (uint32_t)s * STG;
#pragma unroll
        for (int pass = 0; pass < 3; ++pass) {
            const uint32_t aBase = stgBase + ((pass == 2) ? OA_LO : OA_HI);
            const uint32_t bBase = stgBase + ((pass == 1) ? OB_LO : OB_HI);
#pragma unroll
            for (int kk = 0; kk < 32; kk += 16) {
                uint32_t a[2][4];
#pragma unroll
                for (int mi = 0; mi < 2; mi++) {
                    uint32_t addr = aBase +
                        (uint32_t)(((aRow + mi * 16) * KS + kk + aColSel) * 2);
                    ldsm_x4(a[mi][0], a[mi][1], a[mi][2], a[mi][3], addr);
                }
                uint32_t b[8][2];
#pragma unroll
                for (int kh = 0; kh < 2; kh++) {
                    uint32_t r0, r1, r2, r3;
                    uint32_t addr = bBase + (uint32_t)((bRowA * KS + kk + kh * 8) * 2);
                    ldsm_x4(r0, r1, r2, r3, addr);
                    b[0][kh] = r0; b[1][kh] = r1; b[2][kh] = r2; b[3][kh] = r3;
                    addr = bBase + (uint32_t)((bRowB * KS + kk + kh * 8) * 2);
                    ldsm_x4(r0, r1, r2, r3, addr);
                    b[4][kh] = r0; b[5][kh] = r1; b[6][kh] = r2; b[7][kh] = r3;
                }
#pragma unroll
                for (int mi = 0; mi < 2; mi++)
#pragma unroll
                    for (int ni = 0; ni < 8; ni++)
                        mma_bf16(acc[mi][ni], a[mi], b[ni]);
            }
        }
        __syncthreads();
    }

    // ---- epilogue (rows always in-bounds: MPAD padded) ----
#pragma unroll
    for (int mi = 0; mi < 2; mi++) {
        int row0 = rowBase + wm + mi * 16 + (lane >> 2);
        int row1 = row0 + 8;
#pragma unroll
        for (int ni = 0; ni < 8; ni++) {
            int col = wn + ni * 8 + (lane & 3) * 2;
            float bx = 0.f, by = 0.f;
            if (HAS_BIAS) { bx = __ldg(bias + col); by = __ldg(bias + col + 1); }
            float2 o0 = make_float2(acc[mi][ni][0] + bx, acc[mi][ni][1] + by);
            float2 o1 = make_float2(acc[mi][ni][2] + bx, acc[mi][ni][3] + by);
            if (RELU) {
                o0.x = fmaxf(o0.x, 0.f); o0.y = fmaxf(o0.y, 0.f);
                o1.x = fmaxf(o1.x, 0.f); o1.y = fmaxf(o1.y, 0.f);
            }
            if (OUTF32) {
                *(float2*)(C + (size_t)row0 * 256 + col) = o0;
                *(float2*)(C + (size_t)row1 * 256 + col) = o1;
            }
            if (OUTBF16) {
                float hx = __bfloat162float(__float2bfloat16_rn(o0.x));
                float hy = __bfloat162float(__float2bfloat16_rn(o0.y));
                *(uint32_t*)(Chi + (size_t)row0 * 256 + col) = pack_bf16x2(o0.x, o0.y);
                *(uint32_t*)(Clo + (size_t)row0 * 256 + col) =
                    pack_bf16x2(o0.x - hx, o0.y - hy);
                hx = __bfloat162float(__float2bfloat16_rn(o1.x));
                hy = __bfloat162float(__float2bfloat16_rn(o1.y));
                *(uint32_t*)(Chi + (size_t)row1 * 256 + col) = pack_bf16x2(o1.x, o1.y);
                *(uint32_t*)(Clo + (size_t)row1 * 256 + col) =
                    pack_bf16x2(o1.x - hx, o1.y - hy);
            }
        }
    }
}

// ---------------------------------------------------------------------------
// CSR build (fast 3-kernel scan)
// ---------------------------------------------------------------------------
__global__ void zero_cnt_kernel() {
    int i = blockIdx.x * blockDim.x + threadIdx.x;
    if (i < N_NODES) { g_degi[i] = 0; g_cnt[i] = 0; }
}

__global__ void hist_kernel(const int* __restrict__ src, const int* __restrict__ dst) {
    int e = blockIdx.x * blockDim.x + threadIdx.x;
    if (e < E_EDGES) {
        atomicAdd(&g_degi[src[e]], 1);
        atomicAdd(&g_cnt[dst[e]], 1);
    }
}

__global__ void dis_kernel() {
    int i = blockIdx.x * blockDim.x + threadIdx.x;
    if (i < N_NODES) {
        int d = g_degi[i];
        g_dis[i] = (d > 0) ? rsqrtf((float)d) : 0.0f;
    }
}

__global__ void partial_kernel() {
    __shared__ int sh[256];
    int i = blockIdx.x * 256 + threadIdx.x;
    sh[threadIdx.x] = (i < N_NODES) ? g_cnt[i] : 0;
    __syncthreads();
#pragma unroll
    for (int o = 128; o > 0; o >>= 1) {
        if (threadIdx.x < o) sh[threadIdx.x] += sh[threadIdx.x + o];
        __syncthreads();
    }
    if (threadIdx.x == 0) g_bsum[blockIdx.x] = sh[0];
}

__global__ void scan_blocks_kernel() {
    __shared__ int sh[256];
    int tid = threadIdx.x;
    int v = (tid < NBLK) ? g_bsum[tid] : 0;
    sh[tid] = v;
    __syncthreads();
#pragma unroll
    for (int o = 1; o < 256; o <<= 1) {
        int t = (tid >= o) ? sh[tid - o] : 0;
        __syncthreads();
        sh[tid] += t;
        __syncthreads();
    }
    g_boff[tid] = sh[tid] - v;   // exclusive
}

__global__ void apply_kernel() {
    __shared__ int sh[256];
    int tid = threadIdx.x;
    int i = blockIdx.x * 256 + tid;
    int v = (i < N_NODES) ? g_cnt[i] : 0;
    sh[tid] = v;
    __syncthreads();
#pragma unroll
    for (int o = 1; o < 256; o <<= 1) {
        int t = (tid >= o) ? sh[tid - o] : 0;
        __syncthreads();
        sh[tid] += t;
        __syncthreads();
    }
    if (i < N_NODES) {
        int excl = sh[tid] - v + g_boff[blockIdx.x];
        g_rowstart[i] = excl;
        g_cursor[i]   = excl;
    }
}

__global__ void fill_kernel(const int* __restrict__ src, const int* __restrict__ dst) {
    int e = blockIdx.x * blockDim.x + threadIdx.x;
    if (e < E_EDGES) {
        int s = src[e], d = dst[e];
        int pos = atomicAdd(&g_cursor[d], 1);
        g_csr_src[pos] = s;
        g_csr_w[pos]   = -g_dis[s] * g_dis[d];
    }
}

// ---------------------------------------------------------------------------
// Gather: out[n] = base[n] + sum_e w_e * g[src_e]; writes bf16 hi/lo pair.
// One warp per node, 2-edge unroll for MLP.
// ---------------------------------------------------------------------------
__global__ __launch_bounds__(256)
void gather_kernel(const float* __restrict__ g, const float* __restrict__ base,
                   u16* __restrict__ outhi, u16* __restrict__ outlo)
{
    int node = (blockIdx.x * blockDim.x + threadIdx.x) >> 5;
    int lane = threadIdx.x & 31;
    if (node >= N_NODES) return;

    const float* bp = base + (size_t)node * 256 + lane * 8;
    float4 a0 = *(const float4*)(bp);
    float4 a1 = *(const float4*)(bp + 4);

    int p   = g_rowstart[node];
    int end = p + g_cnt[node];

#pragma unroll 1
    for (; p + 1 < end; p += 2) {
        int   s0 = __ldg(&g_csr_src[p]);
        int   s1 = __ldg(&g_csr_src[p + 1]);
        float w0 = __ldg(&g_csr_w[p]);
        float w1 = __ldg(&g_csr_w[p + 1]);
        const float4* gp0 = (const float4*)(g + (size_t)s0 * 256 + lane * 8);
        const float4* gp1 = (const float4*)(g + (size_t)s1 * 256 + lane * 8);
        float4 v00 = gp0[0], v01 = gp0[1];
        float4 v10 = gp1[0], v11 = gp1[1];
        a0.x = fmaf(w0, v00.x, a0.x); a0.y = fmaf(w0, v00.y, a0.y);
        a0.z = fmaf(w0, v00.z, a0.z); a0.w = fmaf(w0, v00.w, a0.w);
        a1.x = fmaf(w0, v01.x, a1.x); a1.y = fmaf(w0, v01.y, a1.y);
        a1.z = fmaf(w0, v01.z, a1.z); a1.w = fmaf(w0, v01.w, a1.w);
        a0.x = fmaf(w1, v10.x, a0.x); a0.y = fmaf(w1, v10.y, a0.y);
        a0.z = fmaf(w1, v10.z, a0.z); a0.w = fmaf(w1, v10.w, a0.w);
        a1.x = fmaf(w1, v11.x, a1.x); a1.y = fmaf(w1, v11.y, a1.y);
        a1.z = fmaf(w1, v11.z, a1.z); a1.w = fmaf(w1, v11.w, a1.w);
    }
    if (p < end) {
        int   s0 = __ldg(&g_csr_src[p]);
        float w0 = __ldg(&g_csr_w[p]);
        const float4* gp0 = (const float4*)(g + (size_t)s0 * 256 + lane * 8);
        float4 v00 = gp0[0], v01 = gp0[1];
        a0.x = fmaf(w0, v00.x, a0.x); a0.y = fmaf(w0, v00.y, a0.y);
        a0.z = fmaf(w0, v00.z, a0.z); a0.w = fmaf(w0, v00.w, a0.w);
        a1.x = fmaf(w0, v01.x, a1.x); a1.y = fmaf(w0, v01.y, a1.y);
        a1.z = fmaf(w0, v01.z, a1.z); a1.w = fmaf(w0, v01.w, a1.w);
    }

    float h0 = __bfloat162float(__float2bfloat16_rn(a0.x));
    float h1 = __bfloat162float(__float2bfloat16_rn(a0.y));
    float h2 = __bfloat162float(__float2bfloat16_rn(a0.z));
    float h3 = __bfloat162float(__float2bfloat16_rn(a0.w));
    float h4 = __bfloat162float(__float2bfloat16_rn(a1.x));
    float h5 = __bfloat162float(__float2bfloat16_rn(a1.y));
    float h6 = __bfloat162float(__float2bfloat16_rn(a1.z));
    float h7 = __bfloat162float(__float2bfloat16_rn(a1.w));

    uint4 hh, ll;
    hh.x = pack_bf16x2(a0.x, a0.y); hh.y = pack_bf16x2(a0.z, a0.w);
    hh.z = pack_bf16x2(a1.x, a1.y); hh.w = pack_bf16x2(a1.z, a1.w);
    ll.x = pack_bf16x2(a0.x - h0, a0.y - h1);
    ll.y = pack_bf16x2(a0.z - h2, a0.w - h3);
    ll.z = pack_bf16x2(a1.x - h4, a1.y - h5);
    ll.w = pack_bf16x2(a1.z - h6, a1.w - h7);

    *(uint4*)(outhi + (size_t)node * 256 + lane * 8) = hh;
    *(uint4*)(outlo + (size_t)node * 256 + lane * 8) = ll;
}

// ---------------------------------------------------------------------------
// Head: out[N,2] = h[N,256] @ W4[2,256]^T + b4. One warp per row.
// ---------------------------------------------------------------------------
__global__ __launch_bounds__(256)
void head_kernel(const float* __restrict__ h, const float* __restrict__ W4,
                 const float* __restrict__ b4, float* __restrict__ out)
{
    int warp = (blockIdx.x * blockDim.x + threadIdx.x) >> 5;
    int lane = threadIdx.x & 31;
    if (warp >= N_NODES) return;

    const float* hr = h + (size_t)warp * 256;
    float s0 = 0.f, s1 = 0.f;
#pragma unroll
    for (int i = 0; i < 8; i++) {
        int c = lane + i * 32;
        float v = hr[c];
        s0 = fmaf(v, W4[c],       s0);
        s1 = fmaf(v, W4[256 + c], s1);
    }
#pragma unroll
    for (int o = 16; o > 0; o >>= 1) {
        s0 += __shfl_down_sync(0xFFFFFFFFu, s0, o);
        s1 += __shfl_down_sync(0xFFFFFFFFu, s1, o);
    }
    if (lane == 0) {
        out[(size_t)warp * 2 + 0] = s0 + b4[0];
        out[(size_t)warp * 2 + 1] = s1 + b4[1];
    }
}

// ---------------------------------------------------------------------------
// Launch sequence
// ---------------------------------------------------------------------------
extern "C" void kernel_launch(void* const* d_in, const int* in_sizes, int n_in,
                              void* d_out, int out_size)
{
    const float* x    = (const float*)d_in[0];
    const int*   ei   = (const int*)  d_in[1];
    const float* W1   = (const float*)d_in[2];
    const float* b1   = (const float*)d_in[3];
    const float* W2   = (const float*)d_in[4];
    const float* b2   = (const float*)d_in[5];
    const float* W3   = (const float*)d_in[6];
    const float* b3   = (const float*)d_in[7];
    const float* W4   = (const float*)d_in[8];
    const float* b4   = (const float*)d_in[9];
    const float* T10  = (const float*)d_in[10];
    const float* T11  = (const float*)d_in[11];
    const float* cb1  = (const float*)d_in[12];
    const float* T20  = (const float*)d_in[13];
    const float* T21  = (const float*)d_in[14];
    const float* cb2  = (const float*)d_in[15];
    float* out = (float*)d_out;

    const int* src = ei;
    const int* dst = ei + E_EDGES;

    float *buf0, *buf1, *buf2;
    u16 *ahi0, *alo0, *ahi1, *alo1, *whi, *wlo;
    cudaGetSymbolAddress((void**)&buf0, g_buf0);
    cudaGetSymbolAddress((void**)&buf1, g_buf1);
    cudaGetSymbolAddress((void**)&buf2, g_buf2);
    cudaGetSymbolAddress((void**)&ahi0, g_ahi0);
    cudaGetSymbolAddress((void**)&alo0, g_alo0);
    cudaGetSymbolAddress((void**)&ahi1, g_ahi1);
    cudaGetSymbolAddress((void**)&alo1, g_alo1);
    cudaGetSymbolAddress((void**)&whi, g_whi);
    cudaGetSymbolAddress((void**)&wlo, g_wlo);

    const int WSZ = HDIM * HDIM;
    const int SMEMSZ = 2 * STG;   // 122880

    cudaFuncSetAttribute(gemm_mma_kernel<true,  true,  false, true>,
                         cudaFuncAttributeMaxDynamicSharedMemorySize, SMEMSZ);
    cudaFuncSetAttribute(gemm_mma_kernel<false, false, true,  false>,
                         cudaFuncAttributeMaxDynamicSharedMemorySize, SMEMSZ);
    cudaFuncSetAttribute(gemm_mma_kernel<false, true,  true,  false>,
                         cudaFuncAttributeMaxDynamicSharedMemorySize, SMEMSZ);
    cudaFuncSetAttribute(gemm_mma_kernel<true,  true,  true,  false>,
                         cudaFuncAttributeMaxDynamicSharedMemorySize, SMEMSZ);

    // --- CSR + norm precompute ---
    zero_cnt_kernel<<<(N_NODES + 255) / 256, 256>>>();
    hist_kernel<<<(E_EDGES + 255) / 256, 256>>>(src, dst);
    dis_kernel<<<(N_NODES + 255) / 256, 256>>>();
    partial_kernel<<<NBLK, 256>>>();
    scan_blocks_kernel<<<1, 256>>>();
    apply_kernel<<<NBLK, 256>>>();
    fill_kernel<<<(E_EDGES + 255) / 256, 256>>>(src, dst);

    // --- splits ---
    split_kernel<<<(N_NODES * HDIM / 4 + 255) / 256, 256>>>(x, ahi0, alo0,
                                                            N_NODES * HDIM / 4);
    const float* wsrc[NW] = {W1, W2, T11, T10, T21, T20, W3};
    for (int i = 0; i < NW; i++)
        split_kernel<<<(WSZ / 4 + 255) / 256, 256>>>(wsrc[i], whi + i * WSZ,
                                                     wlo + i * WSZ, WSZ / 4);

    const int ggrid = MPAD / BM;   // 391
    const int gthr  = (N_NODES * 32 + 255) / 256;

    // h1 = relu(x@W1^T+b1) -> bf16 pair 1
    gemm_mma_kernel<true, true, false, true><<<ggrid, 512, SMEMSZ>>>(
        ahi0, alo0, whi + 0 * WSZ, wlo + 0 * WSZ, b1, nullptr, ahi1, alo1);
    // h2 = relu(h1@W2^T+b2) -> bf16 pair 0
    gemm_mma_kernel<true, true, false, true><<<ggrid, 512, SMEMSZ>>>(
        ahi1, alo1, whi + 1 * WSZ, wlo + 1 * WSZ, b2, nullptr, ahi0, alo0);
    // g = h2@T11^T -> buf0 ; base = h2@T10^T+cb1 -> buf1
    gemm_mma_kernel<false, false, true, false><<<ggrid, 512, SMEMSZ>>>(
        ahi0, alo0, whi + 2 * WSZ, wlo + 2 * WSZ, nullptr, buf0, nullptr, nullptr);
    gemm_mma_kernel<false, true, true, false><<<ggrid, 512, SMEMSZ>>>(
        ahi0, alo0, whi + 3 * WSZ, wlo + 3 * WSZ, cb1, buf1, nullptr, nullptr);
    // out1 = base + S g -> bf16 pair 1
    gather_kernel<<<gthr, 256>>>(buf0, buf1, ahi1, alo1);

    // g = out1@T21^T ; base = out1@T20^T+cb2
    gemm_mma_kernel<false, false, true, false><<<ggrid, 512, SMEMSZ>>>(
        ahi1, alo1, whi + 4 * WSZ, wlo + 4 * WSZ, nullptr, buf0, nullptr, nullptr);
    gemm_mma_kernel<false, true, true, false><<<ggrid, 512, SMEMSZ>>>(
        ahi1, alo1, whi + 5 * WSZ, wlo + 5 * WSZ, cb2, buf1, nullptr, nullptr);
    // out2 = base + S g -> bf16 pair 0
    gather_kernel<<<gthr, 256>>>(buf0, buf1, ahi0, alo0);

    // h3 = relu(out2@W3^T+b3) -> f32 buf2
    gemm_mma_kernel<true, true, true, false><<<ggrid, 512, SMEMSZ>>>(
        ahi0, alo0, whi + 6 * WSZ, wlo + 6 * WSZ, b3, buf2, nullptr, nullptr);
    // out = h3@W4^T + b4
    head_kernel<<<gthr, 256>>>(buf2, W4, b4, out);
}

// round 6
// speedup vs baseline: 2.3755x; 1.0400x over previous
#include <cuda_runtime.h>
#include <cuda_bf16.h>
#include <cstdint>

#define N_NODES 50000
#define MPAD    50048
#define E_EDGES 1600000
#define HDIM    256
#define NBLK    196

typedef unsigned short u16;

// ---------------------------------------------------------------------------
// Static device scratch
// ---------------------------------------------------------------------------
__device__ int   g_degi[N_NODES];
__device__ int   g_cnt[N_NODES];
__device__ int   g_rowstart[N_NODES];
__device__ int   g_cursor[N_NODES];
__device__ float g_dis[N_NODES];
__device__ int   g_csr_src[E_EDGES];
__device__ float g_csr_w[E_EDGES];
__device__ int   g_bsum[256];
__device__ int   g_boff[256];

__device__ float g_h3[(size_t)MPAD * HDIM];

// bf16 activation pairs (pads stay zero: only rows < N_NODES or GEMM-epilogue
// rows are written, identically every launch)
__device__ u16 g_xhi[(size_t)MPAD * HDIM];
__device__ u16 g_xlo[(size_t)MPAD * HDIM];
__device__ u16 g_h1hi[(size_t)MPAD * HDIM];
__device__ u16 g_h1lo[(size_t)MPAD * HDIM];
__device__ u16 g_h2hi[(size_t)MPAD * HDIM];
__device__ u16 g_h2lo[(size_t)MPAD * HDIM];
__device__ u16 g_aghi[(size_t)MPAD * HDIM];
__device__ u16 g_aglo[(size_t)MPAD * HDIM];
__device__ u16 g_o1hi[(size_t)MPAD * HDIM];
__device__ u16 g_o1lo[(size_t)MPAD * HDIM];
__device__ u16 g_o2hi[(size_t)MPAD * HDIM];
__device__ u16 g_o2lo[(size_t)MPAD * HDIM];

// weights: W1,W2,W3 (256 cols); conv concat weights (512 cols)
__device__ u16 g_whi[3 * HDIM * HDIM];
__device__ u16 g_wlo[3 * HDIM * HDIM];
__device__ u16 g_wc1hi[HDIM * 512];
__device__ u16 g_wc1lo[HDIM * 512];
__device__ u16 g_wc2hi[HDIM * 512];
__device__ u16 g_wc2lo[HDIM * 512];

// ---------------------------------------------------------------------------
// helpers
// ---------------------------------------------------------------------------
__device__ __forceinline__ uint32_t pack_bf16x2(float lo, float hi) {
    uint32_t u;
    asm("cvt.rn.bf16x2.f32 %0, %1, %2;" : "=r"(u) : "f"(hi), "f"(lo));
    return u;
}

__device__ __forceinline__ float2 bf2_to_f2(uint32_t u) {
    __nv_bfloat162 b;
    *reinterpret_cast<uint32_t*>(&b) = u;
    return __bfloat1622float2(b);
}

__device__ __forceinline__ void ldsm_x4(uint32_t& r0, uint32_t& r1,
                                        uint32_t& r2, uint32_t& r3, uint32_t addr) {
    asm volatile("ldmatrix.sync.aligned.m8n8.x4.shared.b16 {%0,%1,%2,%3}, [%4];"
                 : "=r"(r0), "=r"(r1), "=r"(r2), "=r"(r3) : "r"(addr));
}

__device__ __forceinline__ void mma_bf16(float c[4], const uint32_t a[4],
                                         const uint32_t b[2]) {
    asm volatile(
        "mma.sync.aligned.m16n8k16.row.col.f32.bf16.bf16.f32 "
        "{%0,%1,%2,%3}, {%4,%5,%6,%7}, {%8,%9}, {%0,%1,%2,%3};"
        : "+f"(c[0]), "+f"(c[1]), "+f"(c[2]), "+f"(c[3])
        : "r"(a[0]), "r"(a[1]), "r"(a[2]), "r"(a[3]), "r"(b[0]), "r"(b[1]));
}

#define CP16(sm, gp) \
    asm volatile("cp.async.cg.shared.global [%0], [%1], 16;" :: "r"(sm), "l"(gp))
#define CPCOMMIT() asm volatile("cp.async.commit_group;")
#define CPWAIT0()  asm volatile("cp.async.wait_group 0;")

// ---------------------------------------------------------------------------
// splits
// ---------------------------------------------------------------------------
__global__ void split_kernel(const float* __restrict__ in, u16* __restrict__ hi,
                             u16* __restrict__ lo, int n4)
{
    int i = blockIdx.x * blockDim.x + threadIdx.x;
    if (i >= n4) return;
    float4 v = ((const float4*)in)[i];
    float hx = __bfloat162float(__float2bfloat16_rn(v.x));
    float hy = __bfloat162float(__float2bfloat16_rn(v.y));
    float hz = __bfloat162float(__float2bfloat16_rn(v.z));
    float hw = __bfloat162float(__float2bfloat16_rn(v.w));
    uint2 h = make_uint2(pack_bf16x2(v.x, v.y), pack_bf16x2(v.z, v.w));
    uint2 l = make_uint2(pack_bf16x2(v.x - hx, v.y - hy),
                         pack_bf16x2(v.z - hz, v.w - hw));
    ((uint2*)hi)[i] = h;
    ((uint2*)lo)[i] = l;
}

// strided split for concat weights: in[256][256] -> out rows stride 512, +colofs
__global__ void split_w_kernel(const float* __restrict__ in, u16* __restrict__ hi,
                               u16* __restrict__ lo, int colofs)
{
    int i = blockIdx.x * blockDim.x + threadIdx.x;   // float4 index, 16384 total
    if (i >= HDIM * HDIM / 4) return;
    int row = i >> 6;
    int col = (i & 63) * 4;
    float4 v = ((const float4*)in)[i];
    float hx = __bfloat162float(__float2bfloat16_rn(v.x));
    float hy = __bfloat162float(__float2bfloat16_rn(v.y));
    float hz = __bfloat162float(__float2bfloat16_rn(v.z));
    float hw = __bfloat162float(__float2bfloat16_rn(v.w));
    uint2 h = make_uint2(pack_bf16x2(v.x, v.y), pack_bf16x2(v.z, v.w));
    uint2 l = make_uint2(pack_bf16x2(v.x - hx, v.y - hy),
                         pack_bf16x2(v.z - hz, v.w - hw));
    size_t o = (size_t)row * 512 + colofs + col;
    *(uint2*)(hi + o) = h;
    *(uint2*)(lo + o) = l;
}

// ---------------------------------------------------------------------------
// GEMM: C[MPAD,256] = A[:,0:K] @ W[256,K]^T (+bias)(+relu)
// K = KCHUNKS*32; chunks >= 8 read the second A pair (K-concat fusion).
// Tile 128x256x32, 512 threads, 2-stage cp.async, bf16 3-pass split, KS=40.
// ---------------------------------------------------------------------------
#define BM   128
#define KS   40
#define STG  61440
#define OA_HI 0
#define OA_LO 10240
#define OB_HI 20480
#define OB_LO 40960

template <int KCHUNKS, bool RELU, bool HAS_BIAS, bool OUTF32>
__global__ __launch_bounds__(512, 1)
void gemm_mma_kernel(const u16* __restrict__ Ahi, const u16* __restrict__ Alo,
                     const u16* __restrict__ A2hi, const u16* __restrict__ A2lo,
                     const u16* __restrict__ Whi, const u16* __restrict__ Wlo,
                     const float* __restrict__ bias,
                     float* __restrict__ C, u16* __restrict__ Chi,
                     u16* __restrict__ Clo)
{
    extern __shared__ char smem[];
    const uint32_t sb = (uint32_t)__cvta_generic_to_shared(smem);
    const int tid  = threadIdx.x;
    const int lane = tid & 31;
    const int wid  = tid >> 5;
    const int wm   = (wid & 3) * 32;
    const int wn   = (wid >> 2) * 64;
    const int rowBase = blockIdx.x * BM;
    const int KTOT = KCHUNKS * 32;

    const int lrow = tid >> 2;
    const int lc8  = (tid & 3) * 8;

    float acc[2][8][4];
#pragma unroll
    for (int mi = 0; mi < 2; mi++)
#pragma unroll
        for (int ni = 0; ni < 8; ni++)
#pragma unroll
            for (int j = 0; j < 4; j++) acc[mi][ni][j] = 0.0f;

    const int aRow = wm + (lane & 15);
    const int aColSel = (lane >> 4) * 8;
    const int bRowA = wn + lane;
    const int bRowB = wn + 32 + lane;

    auto load_chunk = [&](int c, int s) {
        uint32_t base = sb + (uint32_t)s * STG;
        uint32_t so = (uint32_t)(lrow * 80 + lc8 * 2);
        const u16* pah = (c < 8) ? Ahi : A2hi;
        const u16* pal = (c < 8) ? Alo : A2lo;
        int ko = (c & 7) * 32;
        int k0 = c * 32;
        CP16(base + OA_HI + so, pah + (size_t)(rowBase + lrow) * 256 + ko + lc8);
        CP16(base + OA_LO + so, pal + (size_t)(rowBase + lrow) * 256 + ko + lc8);
        CP16(base + OB_HI + so, Whi + (size_t)lrow * KTOT + k0 + lc8);
        CP16(base + OB_LO + so, Wlo + (size_t)lrow * KTOT + k0 + lc8);
        uint32_t so2 = so + 128 * 80;
        CP16(base + OB_HI + so2, Whi + (size_t)(lrow + 128) * KTOT + k0 + lc8);
        CP16(base + OB_LO + so2, Wlo + (size_t)(lrow + 128) * KTOT + k0 + lc8);
    };

    load_chunk(0, 0);
    CPCOMMIT();

#pragma unroll 1
    for (int c = 0; c < KCHUNKS; ++c) {
        const int s = c & 1;
        CPWAIT0();
        __syncthreads();
        if (c + 1 < KCHUNKS) { load_chunk(c + 1, s ^ 1); CPCOMMIT(); }

        const uint32_t stgBase = sb + (uint32_t)s * STG;
#pragma unroll
        for (int pass = 0; pass < 3; ++pass) {
            const uint32_t aBase = stgBase + ((pass == 2) ? OA_LO : OA_HI);
            const uint32_t bBase = stgBase + ((pass == 1) ? OB_LO : OB_HI);
#pragma unroll
            for (int kk = 0; kk < 32; kk += 16) {
                uint32_t a[2][4];
#pragma unroll
                for (int mi = 0; mi < 2; mi++) {
                    uint32_t addr = aBase +
                        (uint32_t)(((aRow + mi * 16) * KS + kk + aColSel) * 2);
                    ldsm_x4(a[mi][0], a[mi][1], a[mi][2], a[mi][3], addr);
                }
                uint32_t b[8][2];
#pragma unroll
                for (int kh = 0; kh < 2; kh++) {
                    uint32_t r0, r1, r2, r3;
                    uint32_t addr = bBase + (uint32_t)((bRowA * KS + kk + kh * 8) * 2);
                    ldsm_x4(r0, r1, r2, r3, addr);
                    b[0][kh] = r0; b[1][kh] = r1; b[2][kh] = r2; b[3][kh] = r3;
                    addr = bBase + (uint32_t)((bRowB * KS + kk + kh * 8) * 2);
                    ldsm_x4(r0, r1, r2, r3, addr);
                    b[4][kh] = r0; b[5][kh] = r1; b[6][kh] = r2; b[7][kh] = r3;
                }
#pragma unroll
                for (int mi = 0; mi < 2; mi++)
#pragma unroll
                    for (int ni = 0; ni < 8; ni++)
                        mma_bf16(acc[mi][ni], a[mi], b[ni]);
            }
        }
        __syncthreads();
    }

    // ---- epilogue ----
#pragma unroll
    for (int mi = 0; mi < 2; mi++) {
        int row0 = rowBase + wm + mi * 16 + (lane >> 2);
        int row1 = row0 + 8;
#pragma unroll
        for (int ni = 0; ni < 8; ni++) {
            int col = wn + ni * 8 + (lane & 3) * 2;
            float bx = 0.f, by = 0.f;
            if (HAS_BIAS) { bx = __ldg(bias + col); by = __ldg(bias + col + 1); }
            float2 o0 = make_float2(acc[mi][ni][0] + bx, acc[mi][ni][1] + by);
            float2 o1 = make_float2(acc[mi][ni][2] + bx, acc[mi][ni][3] + by);
            if (RELU) {
                o0.x = fmaxf(o0.x, 0.f); o0.y = fmaxf(o0.y, 0.f);
                o1.x = fmaxf(o1.x, 0.f); o1.y = fmaxf(o1.y, 0.f);
            }
            if (OUTF32) {
                *(float2*)(C + (size_t)row0 * 256 + col) = o0;
                *(float2*)(C + (size_t)row1 * 256 + col) = o1;
            } else {
                float hx = __bfloat162float(__float2bfloat16_rn(o0.x));
                float hy = __bfloat162float(__float2bfloat16_rn(o0.y));
                *(uint32_t*)(Chi + (size_t)row0 * 256 + col) = pack_bf16x2(o0.x, o0.y);
                *(uint32_t*)(Clo + (size_t)row0 * 256 + col) =
                    pack_bf16x2(o0.x - hx, o0.y - hy);
                hx = __bfloat162float(__float2bfloat16_rn(o1.x));
                hy = __bfloat162float(__float2bfloat16_rn(o1.y));
                *(uint32_t*)(Chi + (size_t)row1 * 256 + col) = pack_bf16x2(o1.x, o1.y);
                *(uint32_t*)(Clo + (size_t)row1 * 256 + col) =
                    pack_bf16x2(o1.x - hx, o1.y - hy);
            }
        }
    }
}

// ---------------------------------------------------------------------------
// CSR build
// ---------------------------------------------------------------------------
__global__ void zero_cnt_kernel() {
    int i = blockIdx.x * blockDim.x + threadIdx.x;
    if (i < N_NODES) { g_degi[i] = 0; g_cnt[i] = 0; }
}

__global__ void hist_kernel(const int* __restrict__ src, const int* __restrict__ dst) {
    int e = blockIdx.x * blockDim.x + threadIdx.x;
    if (e < E_EDGES) {
        atomicAdd(&g_degi[src[e]], 1);
        atomicAdd(&g_cnt[dst[e]], 1);
    }
}

__global__ void dis_kernel() {
    int i = blockIdx.x * blockDim.x + threadIdx.x;
    if (i < N_NODES) {
        int d = g_degi[i];
        g_dis[i] = (d > 0) ? rsqrtf((float)d) : 0.0f;
    }
}

__global__ void partial_kernel() {
    __shared__ int sh[256];
    int i = blockIdx.x * 256 + threadIdx.x;
    sh[threadIdx.x] = (i < N_NODES) ? g_cnt[i] : 0;
    __syncthreads();
#pragma unroll
    for (int o = 128; o > 0; o >>= 1) {
        if (threadIdx.x < o) sh[threadIdx.x] += sh[threadIdx.x + o];
        __syncthreads();
    }
    if (threadIdx.x == 0) g_bsum[blockIdx.x] = sh[0];
}

__global__ void scan_blocks_kernel() {
    __shared__ int sh[256];
    int tid = threadIdx.x;
    int v = (tid < NBLK) ? g_bsum[tid] : 0;
    sh[tid] = v;
    __syncthreads();
#pragma unroll
    for (int o = 1; o < 256; o <<= 1) {
        int t = (tid >= o) ? sh[tid - o] : 0;
        __syncthreads();
        sh[tid] += t;
        __syncthreads();
    }
    g_boff[tid] = sh[tid] - v;
}

__global__ void apply_kernel() {
    __shared__ int sh[256];
    int tid = threadIdx.x;
    int i = blockIdx.x * 256 + tid;
    int v = (i < N_NODES) ? g_cnt[i] : 0;
    sh[tid] = v;
    __syncthreads();
#pragma unroll
    for (int o = 1; o < 256; o <<= 1) {
        int t = (tid >= o) ? sh[tid - o] : 0;
        __syncthreads();
        sh[tid] += t;
        __syncthreads();
    }
    if (i < N_NODES) {
        int excl = sh[tid] - v + g_boff[blockIdx.x];
        g_rowstart[i] = excl;
        g_cursor[i]   = excl;
    }
}

__global__ void fill_kernel(const int* __restrict__ src, const int* __restrict__ dst) {
    int e = blockIdx.x * blockDim.x + threadIdx.x;
    if (e < E_EDGES) {
        int s = src[e], d = dst[e];
        int pos = atomicAdd(&g_cursor[d], 1);
        g_csr_src[pos] = s;
        g_csr_w[pos]   = -g_dis[s] * g_dis[d];
    }
}

// ---------------------------------------------------------------------------
// Gather on bf16 pair: agg[n] = sum_e w_e * (hi+lo)[src_e]; writes bf16 pair.
// One warp per node, 2-edge unroll; output streamed (evict-first) so the
// source rows stay L2-resident.
// ---------------------------------------------------------------------------
__global__ __launch_bounds__(256)
void gather_kernel(const u16* __restrict__ hi, const u16* __restrict__ lo,
                   u16* __restrict__ outhi, u16* __restrict__ outlo)
{
    int node = (blockIdx.x * blockDim.x + threadIdx.x) >> 5;
    int lane = threadIdx.x & 31;
    if (node >= N_NODES) return;

    float a[8] = {0.f, 0.f, 0.f, 0.f, 0.f, 0.f, 0.f, 0.f};

    int p   = g_rowstart[node];
    int end = p + g_cnt[node];

#pragma unroll 1
    for (; p + 1 < end; p += 2) {
        int   s0 = __ldg(&g_csr_src[p]);
        int   s1 = __ldg(&g_csr_src[p + 1]);
        float w0 = __ldg(&g_csr_w[p]);
        float w1 = __ldg(&g_csr_w[p + 1]);
        uint4 h0 = *(const uint4*)(hi + (size_t)s0 * 256 + lane * 8);
        uint4 l0 = *(const uint4*)(lo + (size_t)s0 * 256 + lane * 8);
        uint4 h1 = *(const uint4*)(hi + (size_t)s1 * 256 + lane * 8);
        uint4 l1 = *(const uint4*)(lo + (size_t)s1 * 256 + lane * 8);
#pragma unroll
        for (int q = 0; q < 4; q++) {
            uint32_t hu0 = (&h0.x)[q], lu0 = (&l0.x)[q];
            uint32_t hu1 = (&h1.x)[q], lu1 = (&l1.x)[q];
            float2 fh0 = bf2_to_f2(hu0), fl0 = bf2_to_f2(lu0);
            float2 fh1 = bf2_to_f2(hu1), fl1 = bf2_to_f2(lu1);
            a[q*2]   = fmaf(w0, fh0.x + fl0.x, a[q*2]);
            a[q*2+1] = fmaf(w0, fh0.y + fl0.y, a[q*2+1]);
            a[q*2]   = fmaf(w1, fh1.x + fl1.x, a[q*2]);
            a[q*2+1] = fmaf(w1, fh1.y + fl1.y, a[q*2+1]);
        }
    }
    if (p < end) {
        int   s0 = __ldg(&g_csr_src[p]);
        float w0 = __ldg(&g_csr_w[p]);
        uint4 h0 = *(const uint4*)(hi + (size_t)s0 * 256 + lane * 8);
        uint4 l0 = *(const uint4*)(lo + (size_t)s0 * 256 + lane * 8);
#pragma unroll
        for (int q = 0; q < 4; q++) {
            float2 fh0 = bf2_to_f2((&h0.x)[q]), fl0 = bf2_to_f2((&l0.x)[q]);
            a[q*2]   = fmaf(w0, fh0.x + fl0.x, a[q*2]);
            a[q*2+1] = fmaf(w0, fh0.y + fl0.y, a[q*2+1]);
        }
    }

    uint4 hh, ll;
#pragma unroll
    for (int q = 0; q < 4; q++) {
        float x0 = a[q*2], x1 = a[q*2+1];
        float h0 = __bfloat162float(__float2bfloat16_rn(x0));
        float h1 = __bfloat162float(__float2bfloat16_rn(x1));
        (&hh.x)[q] = pack_bf16x2(x0, x1);
        (&ll.x)[q] = pack_bf16x2(x0 - h0, x1 - h1);
    }
    __stcs((uint4*)(outhi + (size_t)node * 256 + lane * 8), hh);
    __stcs((uint4*)(outlo + (size_t)node * 256 + lane * 8), ll);
}

// ---------------------------------------------------------------------------
// Head: out[N,2] = h[N,256] @ W4[2,256]^T + b4. One warp per row.
// ---------------------------------------------------------------------------
__global__ __launch_bounds__(256)
void head_kernel(const float* __restrict__ h, const float* __restrict__ W4,
                 const float* __restrict__ b4, float* __restrict__ out)
{
    int warp = (blockIdx.x * blockDim.x + threadIdx.x) >> 5;
    int lane = threadIdx.x & 31;
    if (warp >= N_NODES) return;

    const float* hr = h + (size_t)warp * 256;
    float s0 = 0.f, s1 = 0.f;
#pragma unroll
    for (int i = 0; i < 8; i++) {
        int c = lane + i * 32;
        float v = hr[c];
        s0 = fmaf(v, W4[c],       s0);
        s1 = fmaf(v, W4[256 + c], s1);
    }
#pragma unroll
    for (int o = 16; o > 0; o >>= 1) {
        s0 += __shfl_down_sync(0xFFFFFFFFu, s0, o);
        s1 += __shfl_down_sync(0xFFFFFFFFu, s1, o);
    }
    if (lane == 0) {
        out[(size_t)warp * 2 + 0] = s0 + b4[0];
        out[(size_t)warp * 2 + 1] = s1 + b4[1];
    }
}

// ---------------------------------------------------------------------------
// Launch sequence
// ---------------------------------------------------------------------------
extern "C" void kernel_launch(void* const* d_in, const int* in_sizes, int n_in,
                              void* d_out, int out_size)
{
    const float* x    = (const float*)d_in[0];
    const int*   ei   = (const int*)  d_in[1];
    const float* W1   = (const float*)d_in[2];
    const float* b1   = (const float*)d_in[3];
    const float* W2   = (const float*)d_in[4];
    const float* b2   = (const float*)d_in[5];
    const float* W3   = (const float*)d_in[6];
    const float* b3   = (const float*)d_in[7];
    const float* W4   = (const float*)d_in[8];
    const float* b4   = (const float*)d_in[9];
    const float* T10  = (const float*)d_in[10];
    const float* T11  = (const float*)d_in[11];
    const float* cb1  = (const float*)d_in[12];
    const float* T20  = (const float*)d_in[13];
    const float* T21  = (const float*)d_in[14];
    const float* cb2  = (const float*)d_in[15];
    float* out = (float*)d_out;

    const int* src = ei;
    const int* dst = ei + E_EDGES;

    float *h3;
    u16 *xhi, *xlo, *h1hi, *h1lo, *h2hi, *h2lo, *aghi, *aglo;
    u16 *o1hi, *o1lo, *o2hi, *o2lo, *whi, *wlo, *wc1hi, *wc1lo, *wc2hi, *wc2lo;
    cudaGetSymbolAddress((void**)&h3, g_h3);
    cudaGetSymbolAddress((void**)&xhi, g_xhi);
    cudaGetSymbolAddress((void**)&xlo, g_xlo);
    cudaGetSymbolAddress((void**)&h1hi, g_h1hi);
    cudaGetSymbolAddress((void**)&h1lo, g_h1lo);
    cudaGetSymbolAddress((void**)&h2hi, g_h2hi);
    cudaGetSymbolAddress((void**)&h2lo, g_h2lo);
    cudaGetSymbolAddress((void**)&aghi, g_aghi);
    cudaGetSymbolAddress((void**)&aglo, g_aglo);
    cudaGetSymbolAddress((void**)&o1hi, g_o1hi);
    cudaGetSymbolAddress((void**)&o1lo, g_o1lo);
    cudaGetSymbolAddress((void**)&o2hi, g_o2hi);
    cudaGetSymbolAddress((void**)&o2lo, g_o2lo);
    cudaGetSymbolAddress((void**)&whi, g_whi);
    cudaGetSymbolAddress((void**)&wlo, g_wlo);
    cudaGetSymbolAddress((void**)&wc1hi, g_wc1hi);
    cudaGetSymbolAddress((void**)&wc1lo, g_wc1lo);
    cudaGetSymbolAddress((void**)&wc2hi, g_wc2hi);
    cudaGetSymbolAddress((void**)&wc2lo, g_wc2lo);

    const int WSZ = HDIM * HDIM;
    const int SMEMSZ = 2 * STG;

    cudaFuncSetAttribute(gemm_mma_kernel<8,  true,  true, false>,
                         cudaFuncAttributeMaxDynamicSharedMemorySize, SMEMSZ);
    cudaFuncSetAttribute(gemm_mma_kernel<16, false, true, false>,
                         cudaFuncAttributeMaxDynamicSharedMemorySize, SMEMSZ);
    cudaFuncSetAttribute(gemm_mma_kernel<8,  true,  true, true>,
                         cudaFuncAttributeMaxDynamicSharedMemorySize, SMEMSZ);

    const int ggrid = MPAD / BM;    // 391
    const int gthr  = (N_NODES * 32 + 255) / 256;
    const int wblk  = (WSZ / 4 + 255) / 256;

    // --- positions 1-5: splits + first two GEMMs (ncu capture lands here) ---
    split_kernel<<<(N_NODES * HDIM / 4 + 255) / 256, 256>>>(x, xhi, xlo,
                                                            N_NODES * HDIM / 4);
    split_kernel<<<wblk, 256>>>(W1, whi + 0 * WSZ, wlo + 0 * WSZ, WSZ / 4);
    split_kernel<<<wblk, 256>>>(W2, whi + 1 * WSZ, wlo + 1 * WSZ, WSZ / 4);
    gemm_mma_kernel<8, true, true, false><<<ggrid, 512, SMEMSZ>>>(
        xhi, xlo, nullptr, nullptr, whi + 0 * WSZ, wlo + 0 * WSZ, b1,
        nullptr, h1hi, h1lo);
    gemm_mma_kernel<8, true, true, false><<<ggrid, 512, SMEMSZ>>>(
        h1hi, h1lo, nullptr, nullptr, whi + 1 * WSZ, wlo + 1 * WSZ, b2,
        nullptr, h2hi, h2lo);

    // --- CSR + remaining weight splits ---
    zero_cnt_kernel<<<(N_NODES + 255) / 256, 256>>>();
    hist_kernel<<<(E_EDGES + 255) / 256, 256>>>(src, dst);
    dis_kernel<<<(N_NODES + 255) / 256, 256>>>();
    partial_kernel<<<NBLK, 256>>>();
    scan_blocks_kernel<<<1, 256>>>();
    apply_kernel<<<NBLK, 256>>>();
    fill_kernel<<<(E_EDGES + 255) / 256, 256>>>(src, dst);

    split_w_kernel<<<wblk, 256>>>(T10, wc1hi, wc1lo, 0);
    split_w_kernel<<<wblk, 256>>>(T11, wc1hi, wc1lo, 256);
    split_w_kernel<<<wblk, 256>>>(T20, wc2hi, wc2lo, 0);
    split_w_kernel<<<wblk, 256>>>(T21, wc2hi, wc2lo, 256);
    split_kernel<<<wblk, 256>>>(W3, whi + 2 * WSZ, wlo + 2 * WSZ, WSZ / 4);

    // --- conv 1: agg = S h2 ; out1 = [h2, agg] @ [T10;T11]^T + cb1 ---
    gather_kernel<<<gthr, 256>>>(h2hi, h2lo, aghi, aglo);
    gemm_mma_kernel<16, false, true, false><<<ggrid, 512, SMEMSZ>>>(
        h2hi, h2lo, aghi, aglo, wc1hi, wc1lo, cb1, nullptr, o1hi, o1lo);

    // --- conv 2: agg = S out1 ; out2 = [out1, agg] @ [T20;T21]^T + cb2 ---
    gather_kernel<<<gthr, 256>>>(o1hi, o1lo, aghi, aglo);
    gemm_mma_kernel<16, false, true, false><<<ggrid, 512, SMEMSZ>>>(
        o1hi, o1lo, aghi, aglo, wc2hi, wc2lo, cb2, nullptr, o2hi, o2lo);

    // --- h3 = relu(out2@W3^T + b3) ; out = h3@W4^T + b4 ---
    gemm_mma_kernel<8, true, true, true><<<ggrid, 512, SMEMSZ>>>(
        o2hi, o2lo, nullptr, nullptr, whi + 2 * WSZ, wlo + 2 * WSZ, b3,
        h3, nullptr, nullptr);
    head_kernel<<<gthr, 256>>>(h3, W4, b4, out);
}

// round 7
// speedup vs baseline: 2.4666x; 1.0384x over previous
#include <cuda_runtime.h>
#include <cuda_bf16.h>
#include <cstdint>

#define N_NODES 50000
#define MPAD    50048
#define E_EDGES 1600000
#define HDIM    256
#define NBLK    196

typedef unsigned short u16;

// ---------------------------------------------------------------------------
// Static device scratch
// ---------------------------------------------------------------------------
__device__ int   g_degi[N_NODES];
__device__ int   g_cnt[N_NODES];
__device__ int   g_rowstart[N_NODES];
__device__ int   g_cursor[N_NODES];
__device__ float g_dis[N_NODES];
__device__ int   g_csr_src[E_EDGES];
__device__ float g_csr_w[E_EDGES];
__device__ int   g_bsum[256];
__device__ int   g_boff[256];

__device__ float g_h3[(size_t)MPAD * HDIM];

__device__ u16 g_xhi[(size_t)MPAD * HDIM];
__device__ u16 g_xlo[(size_t)MPAD * HDIM];
__device__ u16 g_h1hi[(size_t)MPAD * HDIM];
__device__ u16 g_h1lo[(size_t)MPAD * HDIM];
__device__ u16 g_h2hi[(size_t)MPAD * HDIM];
__device__ u16 g_h2lo[(size_t)MPAD * HDIM];
__device__ u16 g_aghi[(size_t)MPAD * HDIM];
__device__ u16 g_aglo[(size_t)MPAD * HDIM];
__device__ u16 g_o1hi[(size_t)MPAD * HDIM];
__device__ u16 g_o1lo[(size_t)MPAD * HDIM];
__device__ u16 g_o2hi[(size_t)MPAD * HDIM];
__device__ u16 g_o2lo[(size_t)MPAD * HDIM];

__device__ u16 g_whi[3 * HDIM * HDIM];
__device__ u16 g_wlo[3 * HDIM * HDIM];
__device__ u16 g_wc1hi[HDIM * 512];
__device__ u16 g_wc1lo[HDIM * 512];
__device__ u16 g_wc2hi[HDIM * 512];
__device__ u16 g_wc2lo[HDIM * 512];

// ---------------------------------------------------------------------------
// helpers
// ---------------------------------------------------------------------------
__device__ __forceinline__ uint32_t pack_bf16x2(float lo, float hi) {
    uint32_t u;
    asm("cvt.rn.bf16x2.f32 %0, %1, %2;" : "=r"(u) : "f"(hi), "f"(lo));
    return u;
}

__device__ __forceinline__ float2 bf2_to_f2(uint32_t u) {
    __nv_bfloat162 b;
    *reinterpret_cast<uint32_t*>(&b) = u;
    return __bfloat1622float2(b);
}

__device__ __forceinline__ void ldsm_x4(uint32_t& r0, uint32_t& r1,
                                        uint32_t& r2, uint32_t& r3, uint32_t addr) {
    asm volatile("ldmatrix.sync.aligned.m8n8.x4.shared.b16 {%0,%1,%2,%3}, [%4];"
                 : "=r"(r0), "=r"(r1), "=r"(r2), "=r"(r3) : "r"(addr));
}

__device__ __forceinline__ void mma_bf16(float c[4], const uint32_t a[4],
                                         const uint32_t b[2]) {
    asm volatile(
        "mma.sync.aligned.m16n8k16.row.col.f32.bf16.bf16.f32 "
        "{%0,%1,%2,%3}, {%4,%5,%6,%7}, {%8,%9}, {%0,%1,%2,%3};"
        : "+f"(c[0]), "+f"(c[1]), "+f"(c[2]), "+f"(c[3])
        : "r"(a[0]), "r"(a[1]), "r"(a[2]), "r"(a[3]), "r"(b[0]), "r"(b[1]));
}

#define CP16(sm, gp) \
    asm volatile("cp.async.cg.shared.global [%0], [%1], 16;" :: "r"(sm), "l"(gp))
#define CPCOMMIT() asm volatile("cp.async.commit_group;")
#define CPWAIT0()  asm volatile("cp.async.wait_group 0;")

// ---------------------------------------------------------------------------
// splits
// ---------------------------------------------------------------------------
__global__ void split_kernel(const float* __restrict__ in, u16* __restrict__ hi,
                             u16* __restrict__ lo, int n4)
{
    int i = blockIdx.x * blockDim.x + threadIdx.x;
    if (i >= n4) return;
    float4 v = ((const float4*)in)[i];
    float hx = __bfloat162float(__float2bfloat16_rn(v.x));
    float hy = __bfloat162float(__float2bfloat16_rn(v.y));
    float hz = __bfloat162float(__float2bfloat16_rn(v.z));
    float hw = __bfloat162float(__float2bfloat16_rn(v.w));
    uint2 h = make_uint2(pack_bf16x2(v.x, v.y), pack_bf16x2(v.z, v.w));
    uint2 l = make_uint2(pack_bf16x2(v.x - hx, v.y - hy),
                         pack_bf16x2(v.z - hz, v.w - hw));
    ((uint2*)hi)[i] = h;
    ((uint2*)lo)[i] = l;
}

__global__ void split_w_kernel(const float* __restrict__ in, u16* __restrict__ hi,
                               u16* __restrict__ lo, int colofs)
{
    int i = blockIdx.x * blockDim.x + threadIdx.x;
    if (i >= HDIM * HDIM / 4) return;
    int row = i >> 6;
    int col = (i & 63) * 4;
    float4 v = ((const float4*)in)[i];
    float hx = __bfloat162float(__float2bfloat16_rn(v.x));
    float hy = __bfloat162float(__float2bfloat16_rn(v.y));
    float hz = __bfloat162float(__float2bfloat16_rn(v.z));
    float hw = __bfloat162float(__float2bfloat16_rn(v.w));
    uint2 h = make_uint2(pack_bf16x2(v.x, v.y), pack_bf16x2(v.z, v.w));
    uint2 l = make_uint2(pack_bf16x2(v.x - hx, v.y - hy),
                         pack_bf16x2(v.z - hz, v.w - hw));
    size_t o = (size_t)row * 512 + colofs + col;
    *(uint2*)(hi + o) = h;
    *(uint2*)(lo + o) = l;
}

// ---------------------------------------------------------------------------
// GEMM: C[MPAD, colBase:colBase+128] = A[:,0:K] @ W[colBase:+128, K]^T
// Tile 128x128x32, 256 threads, 2 CTAs/SM, 2-stage cp.async, 3-pass bf16 split.
// KCHUNKS=16 reads second A pair for chunks >= 8 (K-concat fusion).
// ---------------------------------------------------------------------------
#define BM   128
#define KS   40
#define STG  40960
#define OA_HI 0
#define OA_LO 10240
#define OB_HI 20480
#define OB_LO 30720

template <int KCHUNKS, bool RELU, bool HAS_BIAS, bool OUTF32>
__global__ __launch_bounds__(256, 2)
void gemm_mma_kernel(const u16* __restrict__ Ahi, const u16* __restrict__ Alo,
                     const u16* __restrict__ A2hi, const u16* __restrict__ A2lo,
                     const u16* __restrict__ Whi, const u16* __restrict__ Wlo,
                     const float* __restrict__ bias,
                     float* __restrict__ C, u16* __restrict__ Chi,
                     u16* __restrict__ Clo)
{
    extern __shared__ char smem[];
    const uint32_t sb = (uint32_t)__cvta_generic_to_shared(smem);
    const int tid  = threadIdx.x;
    const int lane = tid & 31;
    const int wid  = tid >> 5;
    const int wm   = (wid & 3) * 32;
    const int wn   = (wid >> 2) * 64;
    const int rowBase = blockIdx.x * BM;
    const int colBase = blockIdx.y * 128;
    const int KTOT = KCHUNKS * 32;

    float acc[2][8][4];
#pragma unroll
    for (int mi = 0; mi < 2; mi++)
#pragma unroll
        for (int ni = 0; ni < 8; ni++)
#pragma unroll
            for (int j = 0; j < 4; j++) acc[mi][ni][j] = 0.0f;

    const int aRow = wm + (lane & 15);
    const int aColSel = (lane >> 4) * 8;
    const int bRowA = wn + lane;
    const int bRowB = wn + 32 + lane;

    auto load_chunk = [&](int c, int s) {
        uint32_t base = sb + (uint32_t)s * STG;
        const u16* pah = (c < 8) ? Ahi : A2hi;
        const u16* pal = (c < 8) ? Alo : A2lo;
        int ko = (c & 7) * 32;
        int k0 = c * 32;
#pragma unroll
        for (int i = 0; i < 2; i++) {
            int f   = tid + i * 256;
            int row = f >> 2;
            int c8  = (f & 3) * 8;
            uint32_t so = (uint32_t)(row * 80 + c8 * 2);
            CP16(base + OA_HI + so, pah + (size_t)(rowBase + row) * 256 + ko + c8);
            CP16(base + OA_LO + so, pal + (size_t)(rowBase + row) * 256 + ko + c8);
            CP16(base + OB_HI + so, Whi + (size_t)(colBase + row) * KTOT + k0 + c8);
            CP16(base + OB_LO + so, Wlo + (size_t)(colBase + row) * KTOT + k0 + c8);
        }
    };

    load_chunk(0, 0);
    CPCOMMIT();

#pragma unroll 1
    for (int c = 0; c < KCHUNKS; ++c) {
        const int s = c & 1;
        CPWAIT0();
        __syncthreads();
        if (c + 1 < KCHUNKS) { load_chunk(c + 1, s ^ 1); CPCOMMIT(); }

        const uint32_t stgBase = sb + (uint32_t)s * STG;
#pragma unroll
        for (int pass = 0; pass < 3; ++pass) {
            const uint32_t aBase = stgBase + ((pass == 2) ? OA_LO : OA_HI);
            const uint32_t bBase = stgBase + ((pass == 1) ? OB_LO : OB_HI);
#pragma unroll
            for (int kk = 0; kk < 32; kk += 16) {
                uint32_t a[2][4];
#pragma unroll
                for (int mi = 0; mi < 2; mi++) {
                    uint32_t addr = aBase +
                        (uint32_t)(((aRow + mi * 16) * KS + kk + aColSel) * 2);
                    ldsm_x4(a[mi][0], a[mi][1], a[mi][2], a[mi][3], addr);
                }
                uint32_t b[8][2];
#pragma unroll
                for (int kh = 0; kh < 2; kh++) {
                    uint32_t r0, r1, r2, r3;
                    uint32_t addr = bBase + (uint32_t)((bRowA * KS + kk + kh * 8) * 2);
                    ldsm_x4(r0, r1, r2, r3, addr);
                    b[0][kh] = r0; b[1][kh] = r1; b[2][kh] = r2; b[3][kh] = r3;
                    addr = bBase + (uint32_t)((bRowB * KS + kk + kh * 8) * 2);
                    ldsm_x4(r0, r1, r2, r3, addr);
                    b[4][kh] = r0; b[5][kh] = r1; b[6][kh] = r2; b[7][kh] = r3;
                }
#pragma unroll
                for (int mi = 0; mi < 2; mi++)
#pragma unroll
                    for (int ni = 0; ni < 8; ni++)
                        mma_bf16(acc[mi][ni], a[mi], b[ni]);
            }
        }
        __syncthreads();
    }

    // ---- epilogue ----
#pragma unroll
    for (int mi = 0; mi < 2; mi++) {
        int row0 = rowBase + wm + mi * 16 + (lane >> 2);
        int row1 = row0 + 8;
#pragma unroll
        for (int ni = 0; ni < 8; ni++) {
            int col = colBase + wn + ni * 8 + (lane & 3) * 2;
            float bx = 0.f, by = 0.f;
            if (HAS_BIAS) { bx = __ldg(bias + col); by = __ldg(bias + col + 1); }
            float2 o0 = make_float2(acc[mi][ni][0] + bx, acc[mi][ni][1] + by);
            float2 o1 = make_float2(acc[mi][ni][2] + bx, acc[mi][ni][3] + by);
            if (RELU) {
                o0.x = fmaxf(o0.x, 0.f); o0.y = fmaxf(o0.y, 0.f);
                o1.x = fmaxf(o1.x, 0.f); o1.y = fmaxf(o1.y, 0.f);
            }
            if (OUTF32) {
                *(float2*)(C + (size_t)row0 * 256 + col) = o0;
                *(float2*)(C + (size_t)row1 * 256 + col) = o1;
            } else {
                float hx = __bfloat162float(__float2bfloat16_rn(o0.x));
                float hy = __bfloat162float(__float2bfloat16_rn(o0.y));
                *(uint32_t*)(Chi + (size_t)row0 * 256 + col) = pack_bf16x2(o0.x, o0.y);
                *(uint32_t*)(Clo + (size_t)row0 * 256 + col) =
                    pack_bf16x2(o0.x - hx, o0.y - hy);
                hx = __bfloat162float(__float2bfloat16_rn(o1.x));
                hy = __bfloat162float(__float2bfloat16_rn(o1.y));
                *(uint32_t*)(Chi + (size_t)row1 * 256 + col) = pack_bf16x2(o1.x, o1.y);
                *(uint32_t*)(Clo + (size_t)row1 * 256 + col) =
                    pack_bf16x2(o1.x - hx, o1.y - hy);
            }
        }
    }
}

// ---------------------------------------------------------------------------
// CSR build
// ---------------------------------------------------------------------------
__global__ void zero_cnt_kernel() {
    int i = blockIdx.x * blockDim.x + threadIdx.x;
    if (i < N_NODES) { g_degi[i] = 0; g_cnt[i] = 0; }
}

__global__ void hist_kernel(const int* __restrict__ src, const int* __restrict__ dst) {
    int e = blockIdx.x * blockDim.x + threadIdx.x;
    if (e < E_EDGES) {
        atomicAdd(&g_degi[src[e]], 1);
        atomicAdd(&g_cnt[dst[e]], 1);
    }
}

__global__ void dis_kernel() {
    int i = blockIdx.x * blockDim.x + threadIdx.x;
    if (i < N_NODES) {
        int d = g_degi[i];
        g_dis[i] = (d > 0) ? rsqrtf((float)d) : 0.0f;
    }
}

__global__ void partial_kernel() {
    __shared__ int sh[256];
    int i = blockIdx.x * 256 + threadIdx.x;
    sh[threadIdx.x] = (i < N_NODES) ? g_cnt[i] : 0;
    __syncthreads();
#pragma unroll
    for (int o = 128; o > 0; o >>= 1) {
        if (threadIdx.x < o) sh[threadIdx.x] += sh[threadIdx.x + o];
        __syncthreads();
    }
    if (threadIdx.x == 0) g_bsum[blockIdx.x] = sh[0];
}

__global__ void scan_blocks_kernel() {
    __shared__ int sh[256];
    int tid = threadIdx.x;
    int v = (tid < NBLK) ? g_bsum[tid] : 0;
    sh[tid] = v;
    __syncthreads();
#pragma unroll
    for (int o = 1; o < 256; o <<= 1) {
        int t = (tid >= o) ? sh[tid - o] : 0;
        __syncthreads();
        sh[tid] += t;
        __syncthreads();
    }
    g_boff[tid] = sh[tid] - v;
}

__global__ void apply_kernel() {
    __shared__ int sh[256];
    int tid = threadIdx.x;
    int i = blockIdx.x * 256 + tid;
    int v = (i < N_NODES) ? g_cnt[i] : 0;
    sh[tid] = v;
    __syncthreads();
#pragma unroll
    for (int o = 1; o < 256; o <<= 1) {
        int t = (tid >= o) ? sh[tid - o] : 0;
        __syncthreads();
        sh[tid] += t;
        __syncthreads();
    }
    if (i < N_NODES) {
        int excl = sh[tid] - v + g_boff[blockIdx.x];
        g_rowstart[i] = excl;
        g_cursor[i]   = excl;
    }
}

__global__ void fill_kernel(const int* __restrict__ src, const int* __restrict__ dst) {
    int e = blockIdx.x * blockDim.x + threadIdx.x;
    if (e < E_EDGES) {
        int s = src[e], d = dst[e];
        int pos = atomicAdd(&g_cursor[d], 1);
        g_csr_src[pos] = s;
        g_csr_w[pos]   = -g_dis[s] * g_dis[d];
    }
}

// ---------------------------------------------------------------------------
// Gather: agg[n] = sum_e w_e * (hi+lo)[src_e]; writes bf16 pair (streamed).
// ---------------------------------------------------------------------------
__global__ __launch_bounds__(256)
void gather_kernel(const u16* __restrict__ hi, const u16* __restrict__ lo,
                   u16* __restrict__ outhi, u16* __restrict__ outlo)
{
    int node = (blockIdx.x * blockDim.x + threadIdx.x) >> 5;
    int lane = threadIdx.x & 31;
    if (node >= N_NODES) return;

    float a[8] = {0.f, 0.f, 0.f, 0.f, 0.f, 0.f, 0.f, 0.f};

    int p   = g_rowstart[node];
    int end = p + g_cnt[node];

#pragma unroll 1
    for (; p + 1 < end; p += 2) {
        int   s0 = __ldg(&g_csr_src[p]);
        int   s1 = __ldg(&g_csr_src[p + 1]);
        float w0 = __ldg(&g_csr_w[p]);
        float w1 = __ldg(&g_csr_w[p + 1]);
        uint4 h0 = *(const uint4*)(hi + (size_t)s0 * 256 + lane * 8);
        uint4 l0 = *(const uint4*)(lo + (size_t)s0 * 256 + lane * 8);
        uint4 h1 = *(const uint4*)(hi + (size_t)s1 * 256 + lane * 8);
        uint4 l1 = *(const uint4*)(lo + (size_t)s1 * 256 + lane * 8);
#pragma unroll
        for (int q = 0; q < 4; q++) {
            float2 fh0 = bf2_to_f2((&h0.x)[q]), fl0 = bf2_to_f2((&l0.x)[q]);
            float2 fh1 = bf2_to_f2((&h1.x)[q]), fl1 = bf2_to_f2((&l1.x)[q]);
            a[q*2]   = fmaf(w0, fh0.x + fl0.x, a[q*2]);
            a[q*2+1] = fmaf(w0, fh0.y + fl0.y, a[q*2+1]);
            a[q*2]   = fmaf(w1, fh1.x + fl1.x, a[q*2]);
            a[q*2+1] = fmaf(w1, fh1.y + fl1.y, a[q*2+1]);
        }
    }
    if (p < end) {
        int   s0 = __ldg(&g_csr_src[p]);
        float w0 = __ldg(&g_csr_w[p]);
        uint4 h0 = *(const uint4*)(hi + (size_t)s0 * 256 + lane * 8);
        uint4 l0 = *(const uint4*)(lo + (size_t)s0 * 256 + lane * 8);
#pragma unroll
        for (int q = 0; q < 4; q++) {
            float2 fh0 = bf2_to_f2((&h0.x)[q]), fl0 = bf2_to_f2((&l0.x)[q]);
            a[q*2]   = fmaf(w0, fh0.x + fl0.x, a[q*2]);
            a[q*2+1] = fmaf(w0, fh0.y + fl0.y, a[q*2+1]);
        }
    }

    uint4 hh, ll;
#pragma unroll
    for (int q = 0; q < 4; q++) {
        float x0 = a[q*2], x1 = a[q*2+1];
        float h0 = __bfloat162float(__float2bfloat16_rn(x0));
        float h1 = __bfloat162float(__float2bfloat16_rn(x1));
        (&hh.x)[q] = pack_bf16x2(x0, x1);
        (&ll.x)[q] = pack_bf16x2(x0 - h0, x1 - h1);
    }
    __stcs((uint4*)(outhi + (size_t)node * 256 + lane * 8), hh);
    __stcs((uint4*)(outlo + (size_t)node * 256 + lane * 8), ll);
}

// ---------------------------------------------------------------------------
// Head
// ---------------------------------------------------------------------------
__global__ __launch_bounds__(256)
void head_kernel(const float* __restrict__ h, const float* __restrict__ W4,
                 const float* __restrict__ b4, float* __restrict__ out)
{
    int warp = (blockIdx.x * blockDim.x + threadIdx.x) >> 5;
    int lane = threadIdx.x & 31;
    if (warp >= N_NODES) return;

    const float* hr = h + (size_t)warp * 256;
    float s0 = 0.f, s1 = 0.f;
#pragma unroll
    for (int i = 0; i < 8; i++) {
        int c = lane + i * 32;
        float v = hr[c];
        s0 = fmaf(v, W4[c],       s0);
        s1 = fmaf(v, W4[256 + c], s1);
    }
#pragma unroll
    for (int o = 16; o > 0; o >>= 1) {
        s0 += __shfl_down_sync(0xFFFFFFFFu, s0, o);
        s1 += __shfl_down_sync(0xFFFFFFFFu, s1, o);
    }
    if (lane == 0) {
        out[(size_t)warp * 2 + 0] = s0 + b4[0];
        out[(size_t)warp * 2 + 1] = s1 + b4[1];
    }
}

// ---------------------------------------------------------------------------
// Launch sequence
// ---------------------------------------------------------------------------
extern "C" void kernel_launch(void* const* d_in, const int* in_sizes, int n_in,
                              void* d_out, int out_size)
{
    const float* x    = (const float*)d_in[0];
    const int*   ei   = (const int*)  d_in[1];
    const float* W1   = (const float*)d_in[2];
    const float* b1   = (const float*)d_in[3];
    const float* W2   = (const float*)d_in[4];
    const float* b2   = (const float*)d_in[5];
    const float* W3   = (const float*)d_in[6];
    const float* b3   = (const float*)d_in[7];
    const float* W4   = (const float*)d_in[8];
    const float* b4   = (const float*)d_in[9];
    const float* T10  = (const float*)d_in[10];
    const float* T11  = (const float*)d_in[11];
    const float* cb1  = (const float*)d_in[12];
    const float* T20  = (const float*)d_in[13];
    const float* T21  = (const float*)d_in[14];
    const float* cb2  = (const float*)d_in[15];
    float* out = (float*)d_out;

    const int* src = ei;
    const int* dst = ei + E_EDGES;

    float *h3;
    u16 *xhi, *xlo, *h1hi, *h1lo, *h2hi, *h2lo, *aghi, *aglo;
    u16 *o1hi, *o1lo, *o2hi, *o2lo, *whi, *wlo, *wc1hi, *wc1lo, *wc2hi, *wc2lo;
    cudaGetSymbolAddress((void**)&h3, g_h3);
    cudaGetSymbolAddress((void**)&xhi, g_xhi);
    cudaGetSymbolAddress((void**)&xlo, g_xlo);
    cudaGetSymbolAddress((void**)&h1hi, g_h1hi);
    cudaGetSymbolAddress((void**)&h1lo, g_h1lo);
    cudaGetSymbolAddress((void**)&h2hi, g_h2hi);
    cudaGetSymbolAddress((void**)&h2lo, g_h2lo);
    cudaGetSymbolAddress((void**)&aghi, g_aghi);
    cudaGetSymbolAddress((void**)&aglo, g_aglo);
    cudaGetSymbolAddress((void**)&o1hi, g_o1hi);
    cudaGetSymbolAddress((void**)&o1lo, g_o1lo);
    cudaGetSymbolAddress((void**)&o2hi, g_o2hi);
    cudaGetSymbolAddress((void**)&o2lo, g_o2lo);
    cudaGetSymbolAddress((void**)&whi, g_whi);
    cudaGetSymbolAddress((void**)&wlo, g_wlo);
    cudaGetSymbolAddress((void**)&wc1hi, g_wc1hi);
    cudaGetSymbolAddress((void**)&wc1lo, g_wc1lo);
    cudaGetSymbolAddress((void**)&wc2hi, g_wc2hi);
    cudaGetSymbolAddress((void**)&wc2lo, g_wc2lo);

    const int WSZ = HDIM * HDIM;
    const int SMEMSZ = 2 * STG;   // 81920

    cudaFuncSetAttribute(gemm_mma_kernel<8,  true,  true, false>,
                         cudaFuncAttributeMaxDynamicSharedMemorySize, SMEMSZ);
    cudaFuncSetAttribute(gemm_mma_kernel<16, false, true, false>,
                         cudaFuncAttributeMaxDynamicSharedMemorySize, SMEMSZ);
    cudaFuncSetAttribute(gemm_mma_kernel<8,  true,  true, true>,
                         cudaFuncAttributeMaxDynamicSharedMemorySize, SMEMSZ);

    dim3 ggrid(MPAD / BM, 2);    // (391, 2)
    const int gthr  = (N_NODES * 32 + 255) / 256;
    const int wblk  = (WSZ / 4 + 255) / 256;

    // --- positions 1-5: splits + first two GEMMs (ncu capture lands here) ---
    split_kernel<<<(N_NODES * HDIM / 4 + 255) / 256, 256>>>(x, xhi, xlo,
                                                            N_NODES * HDIM / 4);
    split_kernel<<<wblk, 256>>>(W1, whi + 0 * WSZ, wlo + 0 * WSZ, WSZ / 4);
    split_kernel<<<wblk, 256>>>(W2, whi + 1 * WSZ, wlo + 1 * WSZ, WSZ / 4);
    gemm_mma_kernel<8, true, true, false><<<ggrid, 256, SMEMSZ>>>(
        xhi, xlo, nullptr, nullptr, whi + 0 * WSZ, wlo + 0 * WSZ, b1,
        nullptr, h1hi, h1lo);
    gemm_mma_kernel<8, true, true, false><<<ggrid, 256, SMEMSZ>>>(
        h1hi, h1lo, nullptr, nullptr, whi + 1 * WSZ, wlo + 1 * WSZ, b2,
        nullptr, h2hi, h2lo);

    // --- CSR + remaining weight splits ---
    zero_cnt_kernel<<<(N_NODES + 255) / 256, 256>>>();
    hist_kernel<<<(E_EDGES + 255) / 256, 256>>>(src, dst);
    dis_kernel<<<(N_NODES + 255) / 256, 256>>>();
    partial_kernel<<<NBLK, 256>>>();
    scan_blocks_kernel<<<1, 256>>>();
    apply_kernel<<<NBLK, 256>>>();
    fill_kernel<<<(E_EDGES + 255) / 256, 256>>>(src, dst);

    split_w_kernel<<<wblk, 256>>>(T10, wc1hi, wc1lo, 0);
    split_w_kernel<<<wblk, 256>>>(T11, wc1hi, wc1lo, 256);
    split_w_kernel<<<wblk, 256>>>(T20, wc2hi, wc2lo, 0);
    split_w_kernel<<<wblk, 256>>>(T21, wc2hi, wc2lo, 256);
    split_kernel<<<wblk, 256>>>(W3, whi + 2 * WSZ, wlo + 2 * WSZ, WSZ / 4);

    // --- conv 1 ---
    gather_kernel<<<gthr, 256>>>(h2hi, h2lo, aghi, aglo);
    gemm_mma_kernel<16, false, true, false><<<ggrid, 256, SMEMSZ>>>(
        h2hi, h2lo, aghi, aglo, wc1hi, wc1lo, cb1, nullptr, o1hi, o1lo);

    // --- conv 2 ---
    gather_kernel<<<gthr, 256>>>(o1hi, o1lo, aghi, aglo);
    gemm_mma_kernel<16, false, true, false><<<ggrid, 256, SMEMSZ>>>(
        o1hi, o1lo, aghi, aglo, wc2hi, wc2lo, cb2, nullptr, o2hi, o2lo);

    // --- h3 = relu(out2@W3^T + b3) ; out = h3@W4^T + b4 ---
    gemm_mma_kernel<8, true, true, true><<<ggrid, 256, SMEMSZ>>>(
        o2hi, o2lo, nullptr, nullptr, whi + 2 * WSZ, wlo + 2 * WSZ, b3,
        h3, nullptr, nullptr);
    head_kernel<<<gthr, 256>>>(h3, W4, b4, out);
}

// round 8
// speedup vs baseline: 3.0625x; 1.2416x over previous
#include <cuda_runtime.h>
#include <cuda_fp16.h>
#include <cstdint>

#define N_NODES 50000
#define MPAD    50048
#define E_EDGES 1600000
#define HDIM    256
#define NBLK    196

typedef unsigned short u16;

// ---------------------------------------------------------------------------
// Static device scratch
// ---------------------------------------------------------------------------
__device__ int   g_degi[N_NODES];
__device__ int   g_cnt[N_NODES];
__device__ int   g_rowstart[N_NODES];
__device__ int   g_cursor[N_NODES];
__device__ float g_dis[N_NODES];
__device__ int   g_csr_src[E_EDGES];
__device__ float g_csr_w[E_EDGES];
__device__ int   g_bsum[256];
__device__ int   g_boff[256];

__device__ float g_h3[(size_t)MPAD * HDIM];

// fp16 activation pairs
__device__ u16 g_xhi[(size_t)MPAD * HDIM];
__device__ u16 g_xlo[(size_t)MPAD * HDIM];
__device__ u16 g_h1hi[(size_t)MPAD * HDIM];
__device__ u16 g_h1lo[(size_t)MPAD * HDIM];
__device__ u16 g_h2hi[(size_t)MPAD * HDIM];
__device__ u16 g_h2lo[(size_t)MPAD * HDIM];
__device__ u16 g_aghi[(size_t)MPAD * HDIM];
__device__ u16 g_aglo[(size_t)MPAD * HDIM];
__device__ u16 g_o1hi[(size_t)MPAD * HDIM];
__device__ u16 g_o1lo[(size_t)MPAD * HDIM];
__device__ u16 g_o2hi[(size_t)MPAD * HDIM];
__device__ u16 g_o2lo[(size_t)MPAD * HDIM];

// single-fp16 weights: W1,W2,W3 (256 cols) + concat conv weights (512 cols)
__device__ u16 g_w[3 * HDIM * HDIM];
__device__ u16 g_wc1[HDIM * 512];
__device__ u16 g_wc2[HDIM * 512];

// ---------------------------------------------------------------------------
// helpers
// ---------------------------------------------------------------------------
__device__ __forceinline__ uint32_t pack_f16x2(float lo, float hi) {
    __half2 h = __floats2half2_rn(lo, hi);   // low16 = lo, high16 = hi
    return *reinterpret_cast<uint32_t*>(&h);
}

__device__ __forceinline__ float2 f16x2_to_f2(uint32_t u) {
    __half2 h = *reinterpret_cast<__half2*>(&u);
    return __half22float2(h);
}

__device__ __forceinline__ void ldsm_x4(uint32_t& r0, uint32_t& r1,
                                        uint32_t& r2, uint32_t& r3, uint32_t addr) {
    asm volatile("ldmatrix.sync.aligned.m8n8.x4.shared.b16 {%0,%1,%2,%3}, [%4];"
                 : "=r"(r0), "=r"(r1), "=r"(r2), "=r"(r3) : "r"(addr));
}

__device__ __forceinline__ void mma_f16(float c[4], const uint32_t a[4],
                                        const uint32_t b[2]) {
    asm volatile(
        "mma.sync.aligned.m16n8k16.row.col.f32.f16.f16.f32 "
        "{%0,%1,%2,%3}, {%4,%5,%6,%7}, {%8,%9}, {%0,%1,%2,%3};"
        : "+f"(c[0]), "+f"(c[1]), "+f"(c[2]), "+f"(c[3])
        : "r"(a[0]), "r"(a[1]), "r"(a[2]), "r"(a[3]), "r"(b[0]), "r"(b[1]));
}

#define CP16(sm, gp) \
    asm volatile("cp.async.cg.shared.global [%0], [%1], 16;" :: "r"(sm), "l"(gp))
#define CPCOMMIT() asm volatile("cp.async.commit_group;")
#define CPWAIT(n)  asm volatile("cp.async.wait_group %0;" :: "n"(n))

// ---------------------------------------------------------------------------
// splits
// ---------------------------------------------------------------------------
__global__ void split_kernel(const float* __restrict__ in, u16* __restrict__ hi,
                             u16* __restrict__ lo, int n4)
{
    int i = blockIdx.x * blockDim.x + threadIdx.x;
    if (i >= n4) return;
    float4 v = ((const float4*)in)[i];
    float hx = __half2float(__float2half_rn(v.x));
    float hy = __half2float(__float2half_rn(v.y));
    float hz = __half2float(__float2half_rn(v.z));
    float hw = __half2float(__float2half_rn(v.w));
    uint2 h = make_uint2(pack_f16x2(v.x, v.y), pack_f16x2(v.z, v.w));
    uint2 l = make_uint2(pack_f16x2(v.x - hx, v.y - hy),
                         pack_f16x2(v.z - hz, v.w - hw));
    ((uint2*)hi)[i] = h;
    ((uint2*)lo)[i] = l;
}

// round weights to single fp16, contiguous 256-col layout
__global__ void roundw_kernel(const float* __restrict__ in, u16* __restrict__ w)
{
    int i = blockIdx.x * blockDim.x + threadIdx.x;
    if (i >= HDIM * HDIM / 4) return;
    float4 v = ((const float4*)in)[i];
    ((uint2*)w)[i] = make_uint2(pack_f16x2(v.x, v.y), pack_f16x2(v.z, v.w));
}

// round weights to single fp16, strided into 512-col concat layout
__global__ void roundw512_kernel(const float* __restrict__ in, u16* __restrict__ w,
                                 int colofs)
{
    int i = blockIdx.x * blockDim.x + threadIdx.x;
    if (i >= HDIM * HDIM / 4) return;
    int row = i >> 6;
    int col = (i & 63) * 4;
    float4 v = ((const float4*)in)[i];
    uint2 h = make_uint2(pack_f16x2(v.x, v.y), pack_f16x2(v.z, v.w));
    *(uint2*)(w + (size_t)row * 512 + colofs + col) = h;
}

// ---------------------------------------------------------------------------
// GEMM: C[MPAD, colBase:+128] = (Ahi+Alo)[:,0:K] @ W[colBase:+128, 0:K]^T
// fp16 2-pass (A hi/lo, W single). Tile 128x128x32, 256 thr, 2 CTA/SM,
// 3-stage cp.async, B registers reused across hi/lo passes. KS=40 padding.
// ---------------------------------------------------------------------------
#define BM   128
#define KS   40
#define STG  30720
#define OA_HI 0
#define OA_LO 10240
#define OB    20480

template <int KCHUNKS, bool RELU, bool HAS_BIAS, bool OUTF32>
__global__ __launch_bounds__(256, 2)
void gemm_mma_kernel(const u16* __restrict__ Ahi, const u16* __restrict__ Alo,
                     const u16* __restrict__ A2hi, const u16* __restrict__ A2lo,
                     const u16* __restrict__ W,
                     const float* __restrict__ bias,
                     float* __restrict__ C, u16* __restrict__ Chi,
                     u16* __restrict__ Clo)
{
    extern __shared__ char smem[];
    const uint32_t sb = (uint32_t)__cvta_generic_to_shared(smem);
    const int tid  = threadIdx.x;
    const int lane = tid & 31;
    const int wid  = tid >> 5;
    const int wm   = (wid & 3) * 32;
    const int wn   = (wid >> 2) * 64;
    const int rowBase = blockIdx.x * BM;
    const int colBase = blockIdx.y * 128;
    const int KTOT = KCHUNKS * 32;

    float acc[2][8][4];
#pragma unroll
    for (int mi = 0; mi < 2; mi++)
#pragma unroll
        for (int ni = 0; ni < 8; ni++)
#pragma unroll
            for (int j = 0; j < 4; j++) acc[mi][ni][j] = 0.0f;

    const int aRow = wm + (lane & 15);
    const int aColSel = (lane >> 4) * 8;
    const int bRowA = wn + lane;
    const int bRowB = wn + 32 + lane;

    auto load_chunk = [&](int c) {
        uint32_t base = sb + (uint32_t)(c % 3) * STG;
        const u16* pah = (c < 8) ? Ahi : A2hi;
        const u16* pal = (c < 8) ? Alo : A2lo;
        int ko = (c & 7) * 32;
        int k0 = c * 32;
#pragma unroll
        for (int i = 0; i < 2; i++) {
            int f   = tid + i * 256;
            int row = f >> 2;
            int c8  = (f & 3) * 8;
            uint32_t so = (uint32_t)(row * 80 + c8 * 2);
            CP16(base + OA_HI + so, pah + (size_t)(rowBase + row) * 256 + ko + c8);
            CP16(base + OA_LO + so, pal + (size_t)(rowBase + row) * 256 + ko + c8);
            CP16(base + OB + so, W + (size_t)(colBase + row) * KTOT + k0 + c8);
        }
    };

    load_chunk(0); CPCOMMIT();
    if (KCHUNKS > 1) { load_chunk(1); CPCOMMIT(); }

#pragma unroll 1
    for (int c = 0; c < KCHUNKS; ++c) {
        if (c + 2 < KCHUNKS) { load_chunk(c + 2); CPCOMMIT(); CPWAIT(2); }
        else if (c + 1 < KCHUNKS) { CPWAIT(1); }
        else { CPWAIT(0); }
        __syncthreads();

        const uint32_t stgBase = sb + (uint32_t)(c % 3) * STG;
        const uint32_t aHiB = stgBase + OA_HI;
        const uint32_t aLoB = stgBase + OA_LO;
        const uint32_t bB   = stgBase + OB;
#pragma unroll
        for (int kk = 0; kk < 32; kk += 16) {
            // B tiles: loaded once, reused for both hi and lo passes
            uint32_t b[8][2];
#pragma unroll
            for (int kh = 0; kh < 2; kh++) {
                uint32_t r0, r1, r2, r3;
                uint32_t addr = bB + (uint32_t)((bRowA * KS + kk + kh * 8) * 2);
                ldsm_x4(r0, r1, r2, r3, addr);
                b[0][kh] = r0; b[1][kh] = r1; b[2][kh] = r2; b[3][kh] = r3;
                addr = bB + (uint32_t)((bRowB * KS + kk + kh * 8) * 2);
                ldsm_x4(r0, r1, r2, r3, addr);
                b[4][kh] = r0; b[5][kh] = r1; b[6][kh] = r2; b[7][kh] = r3;
            }
            uint32_t ah[2][4], al[2][4];
#pragma unroll
            for (int mi = 0; mi < 2; mi++) {
                uint32_t ao = (uint32_t)(((aRow + mi * 16) * KS + kk + aColSel) * 2);
                ldsm_x4(ah[mi][0], ah[mi][1], ah[mi][2], ah[mi][3], aHiB + ao);
                ldsm_x4(al[mi][0], al[mi][1], al[mi][2], al[mi][3], aLoB + ao);
            }
#pragma unroll
            for (int mi = 0; mi < 2; mi++)
#pragma unroll
                for (int ni = 0; ni < 8; ni++)
                    mma_f16(acc[mi][ni], ah[mi], b[ni]);
#pragma unroll
            for (int mi = 0; mi < 2; mi++)
#pragma unroll
                for (int ni = 0; ni < 8; ni++)
                    mma_f16(acc[mi][ni], al[mi], b[ni]);
        }
        __syncthreads();
    }

    // ---- epilogue ----
#pragma unroll
    for (int mi = 0; mi < 2; mi++) {
        int row0 = rowBase + wm + mi * 16 + (lane >> 2);
        int row1 = row0 + 8;
#pragma unroll
        for (int ni = 0; ni < 8; ni++) {
            int col = colBase + wn + ni * 8 + (lane & 3) * 2;
            float bx = 0.f, by = 0.f;
            if (HAS_BIAS) { bx = __ldg(bias + col); by = __ldg(bias + col + 1); }
            float2 o0 = make_float2(acc[mi][ni][0] + bx, acc[mi][ni][1] + by);
            float2 o1 = make_float2(acc[mi][ni][2] + bx, acc[mi][ni][3] + by);
            if (RELU) {
                o0.x = fmaxf(o0.x, 0.f); o0.y = fmaxf(o0.y, 0.f);
                o1.x = fmaxf(o1.x, 0.f); o1.y = fmaxf(o1.y, 0.f);
            }
            if (OUTF32) {
                *(float2*)(C + (size_t)row0 * 256 + col) = o0;
                *(float2*)(C + (size_t)row1 * 256 + col) = o1;
            } else {
                float hx = __half2float(__float2half_rn(o0.x));
                float hy = __half2float(__float2half_rn(o0.y));
                *(uint32_t*)(Chi + (size_t)row0 * 256 + col) = pack_f16x2(o0.x, o0.y);
                *(uint32_t*)(Clo + (size_t)row0 * 256 + col) =
                    pack_f16x2(o0.x - hx, o0.y - hy);
                hx = __half2float(__float2half_rn(o1.x));
                hy = __half2float(__float2half_rn(o1.y));
                *(uint32_t*)(Chi + (size_t)row1 * 256 + col) = pack_f16x2(o1.x, o1.y);
                *(uint32_t*)(Clo + (size_t)row1 * 256 + col) =
                    pack_f16x2(o1.x - hx, o1.y - hy);
            }
        }
    }
}

// ---------------------------------------------------------------------------
// CSR build
// ---------------------------------------------------------------------------
__global__ void zero_cnt_kernel() {
    int i = blockIdx.x * blockDim.x + threadIdx.x;
    if (i < N_NODES) { g_degi[i] = 0; g_cnt[i] = 0; }
}

__global__ void hist_kernel(const int* __restrict__ src, const int* __restrict__ dst) {
    int e = blockIdx.x * blockDim.x + threadIdx.x;
    if (e < E_EDGES) {
        atomicAdd(&g_degi[src[e]], 1);
        atomicAdd(&g_cnt[dst[e]], 1);
    }
}

__global__ void dis_kernel() {
    int i = blockIdx.x * blockDim.x + threadIdx.x;
    if (i < N_NODES) {
        int d = g_degi[i];
        g_dis[i] = (d > 0) ? rsqrtf((float)d) : 0.0f;
    }
}

__global__ void partial_kernel() {
    __shared__ int sh[256];
    int i = blockIdx.x * 256 + threadIdx.x;
    sh[threadIdx.x] = (i < N_NODES) ? g_cnt[i] : 0;
    __syncthreads();
#pragma unroll
    for (int o = 128; o > 0; o >>= 1) {
        if (threadIdx.x < o) sh[threadIdx.x] += sh[threadIdx.x + o];
        __syncthreads();
    }
    if (threadIdx.x == 0) g_bsum[blockIdx.x] = sh[0];
}

__global__ void scan_blocks_kernel() {
    __shared__ int sh[256];
    int tid = threadIdx.x;
    int v = (tid < NBLK) ? g_bsum[tid] : 0;
    sh[tid] = v;
    __syncthreads();
#pragma unroll
    for (int o = 1; o < 256; o <<= 1) {
        int t = (tid >= o) ? sh[tid - o] : 0;
        __syncthreads();
        sh[tid] += t;
        __syncthreads();
    }
    g_boff[tid] = sh[tid] - v;
}

__global__ void apply_kernel() {
    __shared__ int sh[256];
    int tid = threadIdx.x;
    int i = blockIdx.x * 256 + tid;
    int v = (i < N_NODES) ? g_cnt[i] : 0;
    sh[tid] = v;
    __syncthreads();
#pragma unroll
    for (int o = 1; o < 256; o <<= 1) {
        int t = (tid >= o) ? sh[tid - o] : 0;
        __syncthreads();
        sh[tid] += t;
        __syncthreads();
    }
    if (i < N_NODES) {
        int excl = sh[tid] - v + g_boff[blockIdx.x];
        g_rowstart[i] = excl;
        g_cursor[i]   = excl;
    }
}

__global__ void fill_kernel(const int* __restrict__ src, const int* __restrict__ dst) {
    int e = blockIdx.x * blockDim.x + threadIdx.x;
    if (e < E_EDGES) {
        int s = src[e], d = dst[e];
        int pos = atomicAdd(&g_cursor[d], 1);
        g_csr_src[pos] = s;
        g_csr_w[pos]   = -g_dis[s] * g_dis[d];
    }
}

// ---------------------------------------------------------------------------
// Gather: agg[n] = sum_e w_e * (hi+lo)[src_e]; writes fp16 pair (streamed).
// ---------------------------------------------------------------------------
__global__ __launch_bounds__(256)
void gather_kernel(const u16* __restrict__ hi, const u16* __restrict__ lo,
                   u16* __restrict__ outhi, u16* __restrict__ outlo)
{
    int node = (blockIdx.x * blockDim.x + threadIdx.x) >> 5;
    int lane = threadIdx.x & 31;
    if (node >= N_NODES) return;

    float a[8] = {0.f, 0.f, 0.f, 0.f, 0.f, 0.f, 0.f, 0.f};

    int p   = g_rowstart[node];
    int end = p + g_cnt[node];

#pragma unroll 1
    for (; p + 1 < end; p += 2) {
        int   s0 = __ldg(&g_csr_src[p]);
        int   s1 = __ldg(&g_csr_src[p + 1]);
        float w0 = __ldg(&g_csr_w[p]);
        float w1 = __ldg(&g_csr_w[p + 1]);
        uint4 h0 = *(const uint4*)(hi + (size_t)s0 * 256 + lane * 8);
        uint4 l0 = *(const uint4*)(lo + (size_t)s0 * 256 + lane * 8);
        uint4 h1 = *(const uint4*)(hi + (size_t)s1 * 256 + lane * 8);
        uint4 l1 = *(const uint4*)(lo + (size_t)s1 * 256 + lane * 8);
#pragma unroll
        for (int q = 0; q < 4; q++) {
            float2 fh0 = f16x2_to_f2((&h0.x)[q]), fl0 = f16x2_to_f2((&l0.x)[q]);
            float2 fh1 = f16x2_to_f2((&h1.x)[q]), fl1 = f16x2_to_f2((&l1.x)[q]);
            a[q*2]   = fmaf(w0, fh0.x + fl0.x, a[q*2]);
            a[q*2+1] = fmaf(w0, fh0.y + fl0.y, a[q*2+1]);
            a[q*2]   = fmaf(w1, fh1.x + fl1.x, a[q*2]);
            a[q*2+1] = fmaf(w1, fh1.y + fl1.y, a[q*2+1]);
        }
    }
    if (p < end) {
        int   s0 = __ldg(&g_csr_src[p]);
        float w0 = __ldg(&g_csr_w[p]);
        uint4 h0 = *(const uint4*)(hi + (size_t)s0 * 256 + lane * 8);
        uint4 l0 = *(const uint4*)(lo + (size_t)s0 * 256 + lane * 8);
#pragma unroll
        for (int q = 0; q < 4; q++) {
            float2 fh0 = f16x2_to_f2((&h0.x)[q]), fl0 = f16x2_to_f2((&l0.x)[q]);
            a[q*2]   = fmaf(w0, fh0.x + fl0.x, a[q*2]);
            a[q*2+1] = fmaf(w0, fh0.y + fl0.y, a[q*2+1]);
        }
    }

    uint4 hh, ll;
#pragma unroll
    for (int q = 0; q < 4; q++) {
        float x0 = a[q*2], x1 = a[q*2+1];
        float h0 = __half2float(__float2half_rn(x0));
        float h1 = __half2float(__float2half_rn(x1));
        (&hh.x)[q] = pack_f16x2(x0, x1);
        (&ll.x)[q] = pack_f16x2(x0 - h0, x1 - h1);
    }
    __stcs((uint4*)(outhi + (size_t)node * 256 + lane * 8), hh);
    __stcs((uint4*)(outlo + (size_t)node * 256 + lane * 8), ll);
}

// ---------------------------------------------------------------------------
// Head
// ---------------------------------------------------------------------------
__global__ __launch_bounds__(256)
void head_kernel(const float* __restrict__ h, const float* __restrict__ W4,
                 const float* __restrict__ b4, float* __restrict__ out)
{
    int warp = (blockIdx.x * blockDim.x + threadIdx.x) >> 5;
    int lane = threadIdx.x & 31;
    if (warp >= N_NODES) return;

    const float* hr = h + (size_t)warp * 256;
    float s0 = 0.f, s1 = 0.f;
#pragma unroll
    for (int i = 0; i < 8; i++) {
        int c = lane + i * 32;
        float v = hr[c];
        s0 = fmaf(v, W4[c],       s0);
        s1 = fmaf(v, W4[256 + c], s1);
    }
#pragma unroll
    for (int o = 16; o > 0; o >>= 1) {
        s0 += __shfl_down_sync(0xFFFFFFFFu, s0, o);
        s1 += __shfl_down_sync(0xFFFFFFFFu, s1, o);
    }
    if (lane == 0) {
        out[(size_t)warp * 2 + 0] = s0 + b4[0];
        out[(size_t)warp * 2 + 1] = s1 + b4[1];
    }
}

// ---------------------------------------------------------------------------
// Launch sequence
// ---------------------------------------------------------------------------
extern "C" void kernel_launch(void* const* d_in, const int* in_sizes, int n_in,
                              void* d_out, int out_size)
{
    const float* x    = (const float*)d_in[0];
    const int*   ei   = (const int*)  d_in[1];
    const float* W1   = (const float*)d_in[2];
    const float* b1   = (const float*)d_in[3];
    const float* W2   = (const float*)d_in[4];
    const float* b2   = (const float*)d_in[5];
    const float* W3   = (const float*)d_in[6];
    const float* b3   = (const float*)d_in[7];
    const float* W4   = (const float*)d_in[8];
    const float* b4   = (const float*)d_in[9];
    const float* T10  = (const float*)d_in[10];
    const float* T11  = (const float*)d_in[11];
    const float* cb1  = (const float*)d_in[12];
    const float* T20  = (const float*)d_in[13];
    const float* T21  = (const float*)d_in[14];
    const float* cb2  = (const float*)d_in[15];
    float* out = (float*)d_out;

    const int* src = ei;
    const int* dst = ei + E_EDGES;

    float *h3;
    u16 *xhi, *xlo, *h1hi, *h1lo, *h2hi, *h2lo, *aghi, *aglo;
    u16 *o1hi, *o1lo, *o2hi, *o2lo, *w, *wc1, *wc2;
    cudaGetSymbolAddress((void**)&h3, g_h3);
    cudaGetSymbolAddress((void**)&xhi, g_xhi);
    cudaGetSymbolAddress((void**)&xlo, g_xlo);
    cudaGetSymbolAddress((void**)&h1hi, g_h1hi);
    cudaGetSymbolAddress((void**)&h1lo, g_h1lo);
    cudaGetSymbolAddress((void**)&h2hi, g_h2hi);
    cudaGetSymbolAddress((void**)&h2lo, g_h2lo);
    cudaGetSymbolAddress((void**)&aghi, g_aghi);
    cudaGetSymbolAddress((void**)&aglo, g_aglo);
    cudaGetSymbolAddress((void**)&o1hi, g_o1hi);
    cudaGetSymbolAddress((void**)&o1lo, g_o1lo);
    cudaGetSymbolAddress((void**)&o2hi, g_o2hi);
    cudaGetSymbolAddress((void**)&o2lo, g_o2lo);
    cudaGetSymbolAddress((void**)&w, g_w);
    cudaGetSymbolAddress((void**)&wc1, g_wc1);
    cudaGetSymbolAddress((void**)&wc2, g_wc2);

    const int WSZ = HDIM * HDIM;
    const int SMEMSZ = 3 * STG;   // 92160

    cudaFuncSetAttribute(gemm_mma_kernel<8,  true,  true, false>,
                         cudaFuncAttributeMaxDynamicSharedMemorySize, SMEMSZ);
    cudaFuncSetAttribute(gemm_mma_kernel<16, false, true, false>,
                         cudaFuncAttributeMaxDynamicSharedMemorySize, SMEMSZ);
    cudaFuncSetAttribute(gemm_mma_kernel<8,  true,  true, true>,
                         cudaFuncAttributeMaxDynamicSharedMemorySize, SMEMSZ);

    dim3 ggrid(MPAD / BM, 2);    // (391, 2)
    const int gthr  = (N_NODES * 32 + 255) / 256;
    const int wblk  = (WSZ / 4 + 255) / 256;

    // --- positions 1-5: splits + first two GEMMs (ncu capture lands here) ---
    split_kernel<<<(N_NODES * HDIM / 4 + 255) / 256, 256>>>(x, xhi, xlo,
                                                            N_NODES * HDIM / 4);
    roundw_kernel<<<wblk, 256>>>(W1, w + 0 * WSZ);
    roundw_kernel<<<wblk, 256>>>(W2, w + 1 * WSZ);
    gemm_mma_kernel<8, true, true, false><<<ggrid, 256, SMEMSZ>>>(
        xhi, xlo, nullptr, nullptr, w + 0 * WSZ, b1, nullptr, h1hi, h1lo);
    gemm_mma_kernel<8, true, true, false><<<ggrid, 256, SMEMSZ>>>(
        h1hi, h1lo, nullptr, nullptr, w + 1 * WSZ, b2, nullptr, h2hi, h2lo);

    // --- CSR + remaining weight prep ---
    zero_cnt_kernel<<<(N_NODES + 255) / 256, 256>>>();
    hist_kernel<<<(E_EDGES + 255) / 256, 256>>>(src, dst);
    dis_kernel<<<(N_NODES + 255) / 256, 256>>>();
    partial_kernel<<<NBLK, 256>>>();
    scan_blocks_kernel<<<1, 256>>>();
    apply_kernel<<<NBLK, 256>>>();
    fill_kernel<<<(E_EDGES + 255) / 256, 256>>>(src, dst);

    roundw512_kernel<<<wblk, 256>>>(T10, wc1, 0);
    roundw512_kernel<<<wblk, 256>>>(T11, wc1, 256);
    roundw512_kernel<<<wblk, 256>>>(T20, wc2, 0);
    roundw512_kernel<<<wblk, 256>>>(T21, wc2, 256);
    roundw_kernel<<<wblk, 256>>>(W3, w + 2 * WSZ);

    // --- conv 1: agg = S h2 ; out1 = [h2, agg] @ [T10;T11]^T + cb1 ---
    gather_kernel<<<gthr, 256>>>(h2hi, h2lo, aghi, aglo);
    gemm_mma_kernel<16, false, true, false><<<ggrid, 256, SMEMSZ>>>(
        h2hi, h2lo, aghi, aglo, wc1, cb1, nullptr, o1hi, o1lo);

    // --- conv 2: agg = S out1 ; out2 = [out1, agg] @ [T20;T21]^T + cb2 ---
    gather_kernel<<<gthr, 256>>>(o1hi, o1lo, aghi, aglo);
    gemm_mma_kernel<16, false, true, false><<<ggrid, 256, SMEMSZ>>>(
        o1hi, o1lo, aghi, aglo, wc2, cb2, nullptr, o2hi, o2lo);

    // --- h3 = relu(out2@W3^T + b3) ; out = h3@W4^T + b4 ---
    gemm_mma_kernel<8, true, true, true><<<ggrid, 256, SMEMSZ>>>(
        o2hi, o2lo, nullptr, nullptr, w + 2 * WSZ, b3, h3, nullptr, nullptr);
    head_kernel<<<gthr, 256>>>(h3, W4, b4, out);
}